// round 2
// baseline (speedup 1.0000x reference)
#include <cuda_runtime.h>
#include <cuda_bf16.h>
#include <cstdint>
#include <math.h>

#define BB   2
#define SS   4096
#define DD   1024
#define HH   16
#define DKK  64
#define BLL  128
#define GG   16
#define GLL  256
#define NBUCK 32
#define NEGV (-1e10f)

// ---------------- scratch (device globals: allocation-free) ----------------
__device__ float g_q  [BB*SS*DD];
__device__ float g_k  [BB*SS*DD];
__device__ float g_v  [BB*SS*DD];
__device__ float g_ctx[BB*SS*DD];
__device__ float g_gi [BB*GLL*DD];
__device__ float g_sk [BB*GLL*DD];
__device__ float g_sv [BB*GLL*DD];
__device__ float g_lbias[HH*BLL*3*BLL];   // [h][qi][j]  (pb, + NEG if |rel|>=BL)
__device__ float g_sbias[HH*257*GLL];     // [h][bid+1][g]
__device__ int   g_bid [BB*SS];
__device__ int   g_gseg[BB*GLL];

// ---------------- T5 bidirectional relative bucket ----------------
__device__ __forceinline__ int rel_bucket(int rp) {
    int rb = (rp > 0) ? (NBUCK / 2) : 0;     // 16
    int a  = rp < 0 ? -rp : rp;
    if (a < 8) return rb + a;                 // max_exact = 8
    float rf = (float)a;
    // 8 + log(a/8)/log(16) * 8
    int large = 8 + (int)(logf(rf * 0.125f) * (8.0f / 2.772588722239781f));
    if (large > 15) large = 15;
    return rb + large;
}

// ---------------- block ids / global segments (generic in mask) ----------------
__global__ void k_block_ids(const int* __restrict__ mask) {
    int b = blockIdx.x;
    __shared__ int s_cnt, s_max;
    if (threadIdx.x == 0) { s_cnt = 0; s_max = -1; }
    __syncthreads();
    int lc = 0;
    for (int i = threadIdx.x; i < SS; i += blockDim.x)
        if (((i & (GG - 1)) == GG - 1) && mask[b * SS + i] != 0) lc++;
    atomicAdd(&s_cnt, lc);
    __syncthreads();
    int full = s_cnt - 1;
    int lm = -1;
    for (int i = threadIdx.x; i < SS; i += blockDim.x) {
        int id;
        if (mask[b * SS + i] != 0) { id = i / GG; if (id > full) id = full; }
        else id = -1;
        g_bid[b * SS + i] = id;
        if (id > lm) lm = id;
    }
    atomicMax(&s_max, lm);
    __syncthreads();
    for (int g = threadIdx.x; g < GLL; g += blockDim.x)
        g_gseg[b * GLL + g] = (g <= s_max) ? 1 : 0;
}

// ---------------- global aggregates + RMSNorm ----------------
__global__ void k_global_agg(const float* __restrict__ hs, const float* __restrict__ gln_w) {
    int g = blockIdx.x, b = blockIdx.y;
    int t = threadIdx.x;                       // 256 threads, 4 columns each
    float acc0 = 0.f, acc1 = 0.f, acc2 = 0.f, acc3 = 0.f;
#pragma unroll 1
    for (int s = 0; s < SS; s++) {
        if (g_bid[b * SS + s] == g) {
            const float* row = hs + ((size_t)(b * SS + s)) * DD;
            acc0 += row[t];
            acc1 += row[t + 256];
            acc2 += row[t + 512];
            acc3 += row[t + 768];
        }
    }
    __shared__ float red[256];
    red[t] = acc0 * acc0 + acc1 * acc1 + acc2 * acc2 + acc3 * acc3;
    __syncthreads();
    for (int off = 128; off > 0; off >>= 1) {
        if (t < off) red[t] += red[t + off];
        __syncthreads();
    }
    float var = red[0] * (1.0f / (float)DD);
    float sc = rsqrtf(var + 1e-6f);
    float* out = g_gi + ((size_t)(b * GLL + g)) * DD;
    out[t]       = acc0 * sc * gln_w[t];
    out[t + 256] = acc1 * sc * gln_w[t + 256];
    out[t + 512] = acc2 * sc * gln_w[t + 512];
    out[t + 768] = acc3 * sc * gln_w[t + 768];
}

// ---------------- bias tables ----------------
__global__ void k_localbias(const float* __restrict__ rel_bias) {
    int idx = blockIdx.x * blockDim.x + threadIdx.x;
    if (idx >= HH * BLL * 3 * BLL) return;
    int h  = idx / (BLL * 3 * BLL);
    int r  = idx % (BLL * 3 * BLL);
    int qi = r / (3 * BLL);
    int j  = r % (3 * BLL);
    int rel = j - BLL - qi;
    float v = rel_bias[rel_bucket(rel) * HH + h];
    if (!(rel > -BLL && rel < BLL)) v += NEGV;
    g_lbias[idx] = v;
}

__global__ void k_sidebias(const float* __restrict__ grel) {
    int idx = blockIdx.x * blockDim.x + threadIdx.x;
    if (idx >= HH * 257 * GLL) return;
    int h    = idx / (257 * GLL);
    int r    = idx % (257 * GLL);
    int bidp = r / GLL;        // bid + 1
    int g    = r % GLL;
    int srp  = g - (bidp - 1);
    g_sbias[idx] = grel[rel_bucket(srp) * HH + h];
}

// ---------------- fp32 SGEMM: C[M,N] = A[M,K] @ W[K,N], row-major ----------------
__global__ __launch_bounds__(256)
void sgemm128(const float* __restrict__ A, const float* __restrict__ Bw,
              float* __restrict__ C, int M, int N, int K) {
    const int BM = 128, BN = 128, BK = 8;
    __shared__ float As[BK][BM];
    __shared__ float Bs[BK][BN];
    int tid = threadIdx.x;
    int bx = blockIdx.x;   // N tile
    int by = blockIdx.y;   // M tile
    int arow = tid >> 1, acol = (tid & 1) * 4;
    int brow = tid >> 5, bcol = (tid & 31) * 4;
    int tr = (tid / 16) * 8, tc = (tid % 16) * 8;

    float acc[8][8];
#pragma unroll
    for (int i = 0; i < 8; i++)
#pragma unroll
        for (int j = 0; j < 8; j++) acc[i][j] = 0.f;

    const float* Ap = A + (size_t)(by * BM + arow) * K + acol;
    const float* Bp = Bw + (size_t)brow * N + bx * BN + bcol;

    for (int k0 = 0; k0 < K; k0 += BK) {
        float4 a = *(const float4*)(Ap + k0);
        As[acol + 0][arow] = a.x;
        As[acol + 1][arow] = a.y;
        As[acol + 2][arow] = a.z;
        As[acol + 3][arow] = a.w;
        *(float4*)&Bs[brow][bcol] = *(const float4*)(Bp + (size_t)k0 * N);
        __syncthreads();
#pragma unroll
        for (int k = 0; k < BK; k++) {
            float ra[8], rb[8];
            *(float4*)(ra)     = *(float4*)&As[k][tr];
            *(float4*)(ra + 4) = *(float4*)&As[k][tr + 4];
            *(float4*)(rb)     = *(float4*)&Bs[k][tc];
            *(float4*)(rb + 4) = *(float4*)&Bs[k][tc + 4];
#pragma unroll
            for (int i = 0; i < 8; i++)
#pragma unroll
                for (int j = 0; j < 8; j++)
                    acc[i][j] += ra[i] * rb[j];
        }
        __syncthreads();
    }
    float* Cb = C + (size_t)(by * BM + tr) * N + bx * BN + tc;
#pragma unroll
    for (int i = 0; i < 8; i++) {
        *(float4*)(Cb + (size_t)i * N)     = make_float4(acc[i][0], acc[i][1], acc[i][2], acc[i][3]);
        *(float4*)(Cb + (size_t)i * N + 4) = make_float4(acc[i][4], acc[i][5], acc[i][6], acc[i][7]);
    }
}

// ---------------- attention: one CTA per (h, n, b); thread = one q row ----------------
#define CHUNK 16
#define NKEY  (3 * BLL + GLL)   // 640

__global__ __launch_bounds__(128)
void k_attn(const int* __restrict__ mask) {
    int h = blockIdx.x;
    int n = blockIdx.y;
    int b = blockIdx.z;
    int qi = threadIdx.x;
    int sq = n * BLL + qi;

    // q row into registers
    float4 q4[16];
    const float4* qsrc = (const float4*)(g_q + ((size_t)(b * SS + sq)) * DD + h * DKK);
#pragma unroll
    for (int i = 0; i < 16; i++) q4[i] = qsrc[i];

    int maskq = mask[b * SS + sq];
    int bidq  = g_bid[b * SS + sq];
    const float* ltab = g_lbias + ((size_t)(h * BLL + qi)) * (3 * BLL);
    const float* stab = g_sbias + ((size_t)(h * 257 + (bidq + 1))) * GLL;

    __shared__ float ks[CHUNK][DKK];
    __shared__ float vs[CHUNK][DKK];

    float4 acc4[16];
#pragma unroll
    for (int i = 0; i < 16; i++) acc4[i] = make_float4(0.f, 0.f, 0.f, 0.f);
    float m = -1e30f, l = 0.f;

    int lrow = threadIdx.x >> 3;          // 0..15
    int lcol = (threadIdx.x & 7) * 8;     // 0..56

    for (int c = 0; c < NKEY / CHUNK; c++) {
        int j0 = c * CHUNK;
        // cooperative stage of k/v chunk
        {
            int j = j0 + lrow;
            const float *ksrc = nullptr, *vsrc = nullptr;
            bool valid;
            if (j < 3 * BLL) {
                int t = (n - 1) * BLL + j;
                valid = (t >= 0) && (t < SS);
                if (valid) {
                    size_t off = ((size_t)(b * SS + t)) * DD + h * DKK + lcol;
                    ksrc = g_k + off; vsrc = g_v + off;
                }
            } else {
                int gI = j - 3 * BLL;
                valid = true;
                size_t off = ((size_t)(b * GLL + gI)) * DD + h * DKK + lcol;
                ksrc = g_sk + off; vsrc = g_sv + off;
            }
            float4 k0v, k1v, v0v, v1v;
            if (valid) {
                k0v = *(const float4*)(ksrc);     k1v = *(const float4*)(ksrc + 4);
                v0v = *(const float4*)(vsrc);     v1v = *(const float4*)(vsrc + 4);
            } else {
                k0v = k1v = v0v = v1v = make_float4(0.f, 0.f, 0.f, 0.f);
            }
            *(float4*)&ks[lrow][lcol]     = k0v;
            *(float4*)&ks[lrow][lcol + 4] = k1v;
            *(float4*)&vs[lrow][lcol]     = v0v;
            *(float4*)&vs[lrow][lcol + 4] = v1v;
        }
        __syncthreads();

        float sc[CHUNK];
#pragma unroll
        for (int j2 = 0; j2 < CHUNK; j2++) {
            int j = j0 + j2;
            const float4* kr = (const float4*)ks[j2];
            float s = 0.f;
#pragma unroll
            for (int i = 0; i < 16; i++) {
                float4 kk = kr[i];
                s += q4[i].x * kk.x + q4[i].y * kk.y + q4[i].z * kk.z + q4[i].w * kk.w;
            }
            float bias;
            if (j < 3 * BLL) {
                int t = (n - 1) * BLL + j;
                bias = ltab[j];
                bool ok = (t >= 0) && (t < SS);
                if (ok) ok = (mask[b * SS + t] != 0);
                ok = ok && (maskq != 0);
                if (!ok) bias += NEGV;
            } else {
                int gI = j - 3 * BLL;
                bias = stab[gI];
                if (maskq != g_gseg[b * GLL + gI]) bias += NEGV;
            }
            sc[j2] = s + bias;
        }

        // chunk-granular online softmax
        float cm = sc[0];
#pragma unroll
        for (int j2 = 1; j2 < CHUNK; j2++) cm = fmaxf(cm, sc[j2]);
        float nm = fmaxf(m, cm);
        float rs = __expf(m - nm);
        l *= rs;
#pragma unroll
        for (int i = 0; i < 16; i++) {
            acc4[i].x *= rs; acc4[i].y *= rs; acc4[i].z *= rs; acc4[i].w *= rs;
        }
#pragma unroll
        for (int j2 = 0; j2 < CHUNK; j2++) {
            float p = __expf(sc[j2] - nm);
            l += p;
            const float4* vr = (const float4*)vs[j2];
#pragma unroll
            for (int i = 0; i < 16; i++) {
                float4 vv = vr[i];
                acc4[i].x += p * vv.x; acc4[i].y += p * vv.y;
                acc4[i].z += p * vv.z; acc4[i].w += p * vv.w;
            }
        }
        m = nm;
        __syncthreads();
    }

    float inv = 1.0f / l;
    float4* out = (float4*)(g_ctx + ((size_t)(b * SS + sq)) * DD + h * DKK);
#pragma unroll
    for (int i = 0; i < 16; i++) {
        float4 o = acc4[i];
        o.x *= inv; o.y *= inv; o.z *= inv; o.w *= inv;
        out[i] = o;
    }
}

// ---------------- launch ----------------
extern "C" void kernel_launch(void* const* d_in, const int* in_sizes, int n_in,
                              void* d_out, int out_size) {
    const float* hs   = (const float*)d_in[0];
    const float* Wq   = (const float*)d_in[1];
    const float* Wk   = (const float*)d_in[2];
    const float* Wv   = (const float*)d_in[3];
    const float* Wo   = (const float*)d_in[4];
    const float* relb = (const float*)d_in[5];
    const float* grel = (const float*)d_in[6];
    const float* gln  = (const float*)d_in[7];
    const int*   mask = (const int*)d_in[8];
    float* out = (float*)d_out;

    float* p_q;   cudaGetSymbolAddress((void**)&p_q,   g_q);
    float* p_k;   cudaGetSymbolAddress((void**)&p_k,   g_k);
    float* p_v;   cudaGetSymbolAddress((void**)&p_v,   g_v);
    float* p_ctx; cudaGetSymbolAddress((void**)&p_ctx, g_ctx);
    float* p_gi;  cudaGetSymbolAddress((void**)&p_gi,  g_gi);
    float* p_sk;  cudaGetSymbolAddress((void**)&p_sk,  g_sk);
    float* p_sv;  cudaGetSymbolAddress((void**)&p_sv,  g_sv);

    k_block_ids<<<BB, 256>>>(mask);
    k_global_agg<<<dim3(GLL, BB), 256>>>(hs, gln);

    {
        int n1 = HH * BLL * 3 * BLL;
        k_localbias<<<(n1 + 255) / 256, 256>>>(relb);
        int n2 = HH * 257 * GLL;
        k_sidebias<<<(n2 + 255) / 256, 256>>>(grel);
    }

    dim3 gBig(DD / 128, (BB * SS) / 128);   // (8, 64)
    dim3 gSm(DD / 128, (BB * GLL) / 128);   // (8, 4)
    sgemm128<<<gBig, 256>>>(hs, Wq, p_q, BB * SS, DD, DD);
    sgemm128<<<gBig, 256>>>(hs, Wk, p_k, BB * SS, DD, DD);
    sgemm128<<<gBig, 256>>>(hs, Wv, p_v, BB * SS, DD, DD);
    sgemm128<<<gSm, 256>>>(p_gi, Wk, p_sk, BB * GLL, DD, DD);
    sgemm128<<<gSm, 256>>>(p_gi, Wv, p_sv, BB * GLL, DD, DD);

    k_attn<<<dim3(HH, SS / BLL, BB), 128>>>(mask);

    sgemm128<<<gBig, 256>>>(p_ctx, Wo, out, BB * SS, DD, DD);
}

// round 5
// speedup vs baseline: 1.4365x; 1.4365x over previous
#include <cuda_runtime.h>
#include <cuda_bf16.h>
#include <cstdint>
#include <math.h>

#define BB   2
#define SS   4096
#define DD   1024
#define HH   16
#define DKK  64
#define BLL  128
#define GG   16
#define GLL  256
#define NBUCK 32
#define NEGV (-1e10f)

// ---------------- scratch (device globals: allocation-free) ----------------
__device__ float g_q  [BB*SS*DD];
__device__ float g_k  [BB*SS*DD];
__device__ float g_v  [BB*SS*DD];
__device__ float g_ctx[BB*SS*DD];
__device__ float g_gi [BB*GLL*DD];
__device__ float g_sk [BB*GLL*DD];
__device__ float g_sv [BB*GLL*DD];
__device__ float g_lbias[HH*BLL*3*BLL];
__device__ float g_sbias[HH*257*GLL];
__device__ int   g_bid [BB*SS];
__device__ int   g_gseg[BB*GLL];

// bf16 hi/lo split buffers
__device__ __nv_bfloat16 g_hs_hi [BB*SS*DD];
__device__ __nv_bfloat16 g_hs_lo [BB*SS*DD];
__device__ __nv_bfloat16 g_ctx_hi[BB*SS*DD];
__device__ __nv_bfloat16 g_ctx_lo[BB*SS*DD];
__device__ __nv_bfloat16 g_gi_hi [BB*GLL*DD];
__device__ __nv_bfloat16 g_gi_lo [BB*GLL*DD];
__device__ __nv_bfloat16 g_w_hi  [4][DD*DD];   // Wq, Wk, Wv, Wo
__device__ __nv_bfloat16 g_w_lo  [4][DD*DD];

// ---------------- helpers ----------------
__device__ __forceinline__ uint32_t smem_u32(const void* p) {
    uint32_t a;
    asm("{ .reg .u64 t; cvta.to.shared.u64 t, %1; cvt.u32.u64 %0, t; }" : "=r"(a) : "l"(p));
    return a;
}

#define CP16(dst, src) asm volatile("cp.async.cg.shared.global [%0], [%1], 16;" :: "r"(dst), "l"(src) : "memory")
#define CP_COMMIT()    asm volatile("cp.async.commit_group;" ::: "memory")
#define CP_WAIT1()     asm volatile("cp.async.wait_group 1;" ::: "memory")
#define CP_WAIT0()     asm volatile("cp.async.wait_group 0;" ::: "memory")

__device__ __forceinline__ void ldsm4(uint32_t* r, uint32_t a) {
    asm volatile("ldmatrix.sync.aligned.m8n8.x4.shared.b16 {%0,%1,%2,%3}, [%4];"
        : "=r"(r[0]), "=r"(r[1]), "=r"(r[2]), "=r"(r[3]) : "r"(a));
}
__device__ __forceinline__ void ldsm4t(uint32_t* r, uint32_t a) {
    asm volatile("ldmatrix.sync.aligned.m8n8.x4.trans.shared.b16 {%0,%1,%2,%3}, [%4];"
        : "=r"(r[0]), "=r"(r[1]), "=r"(r[2]), "=r"(r[3]) : "r"(a));
}
__device__ __forceinline__ void mma_bf16(float* d, const uint32_t* a, uint32_t b0, uint32_t b1) {
    asm volatile("mma.sync.aligned.m16n8k16.row.col.f32.bf16.bf16.f32 "
        "{%0,%1,%2,%3}, {%4,%5,%6,%7}, {%8,%9}, {%0,%1,%2,%3};"
        : "+f"(d[0]), "+f"(d[1]), "+f"(d[2]), "+f"(d[3])
        : "r"(a[0]), "r"(a[1]), "r"(a[2]), "r"(a[3]), "r"(b0), "r"(b1));
}

// ---------------- fp32 -> bf16 hi/lo split ----------------
__global__ void k_split(const float4* __restrict__ src,
                        uint2* __restrict__ hi, uint2* __restrict__ lo, int n4) {
    int i = blockIdx.x * 256 + threadIdx.x;
    if (i >= n4) return;
    float4 a = src[i];
    __nv_bfloat162 h01 = __floats2bfloat162_rn(a.x, a.y);
    __nv_bfloat162 h23 = __floats2bfloat162_rn(a.z, a.w);
    float l0 = a.x - __bfloat162float(h01.x);
    float l1 = a.y - __bfloat162float(h01.y);
    float l2 = a.z - __bfloat162float(h23.x);
    float l3 = a.w - __bfloat162float(h23.y);
    __nv_bfloat162 q01 = __floats2bfloat162_rn(l0, l1);
    __nv_bfloat162 q23 = __floats2bfloat162_rn(l2, l3);
    hi[i] = make_uint2(*(uint32_t*)&h01, *(uint32_t*)&h23);
    lo[i] = make_uint2(*(uint32_t*)&q01, *(uint32_t*)&q23);
}

// ============ bf16-split GEMM: C[M,N] = A[M,K] @ W[K,N] ============
// smem layout (halves): per stage: Ahi[128*40] Alo[128*40] Bhi[32*136] Blo[32*136]
#define SH_A0   0
#define SH_A1   5120
#define SH_B0   10240
#define SH_B1   14592
#define SH_STG  18944
#define BGE_SMEM_BYTES (2 * SH_STG * 2)

__global__ __launch_bounds__(256, 1)
void bgemm(const __nv_bfloat16* __restrict__ Ahi, const __nv_bfloat16* __restrict__ Alo,
           const __nv_bfloat16* __restrict__ Bhi, const __nv_bfloat16* __restrict__ Blo,
           float* __restrict__ C, int M, int N, int K) {
    extern __shared__ __nv_bfloat16 sh[];
    uint32_t sbase = smem_u32(sh);

    int tid = threadIdx.x;
    int wid = tid >> 5, lane = tid & 31;
    int wm = wid & 3, wn = wid >> 2;
    int bx = blockIdx.x, by = blockIdx.y;

    float acc[2][8][4];
#pragma unroll
    for (int mt = 0; mt < 2; mt++)
#pragma unroll
        for (int nt = 0; nt < 8; nt++)
#pragma unroll
            for (int j = 0; j < 4; j++) acc[mt][nt][j] = 0.f;

    // per-thread load indices (constant across iterations)
    int ar0 = tid >> 2,          ac0 = (tid & 3) * 8;          // A: i = tid
    int ar1 = (tid + 256) >> 2,  ac1 = ((tid + 256) & 3) * 8;  //    i = tid+256
    int br0 = tid >> 4,          bc0 = (tid & 15) * 8;
    int br1 = (tid + 256) >> 4,  bc1 = ((tid + 256) & 15) * 8;

    auto load_stage = [&](int c, int stage) {
        int k0 = c * 32;
        uint32_t s0 = sbase + (uint32_t)(stage * SH_STG) * 2;
        // A hi/lo
        {
            size_t g0 = (size_t)(by * 128 + ar0) * K + k0 + ac0;
            size_t g1 = (size_t)(by * 128 + ar1) * K + k0 + ac1;
            uint32_t d0 = s0 + (SH_A0 + ar0 * 40 + ac0) * 2;
            uint32_t d1 = s0 + (SH_A0 + ar1 * 40 + ac1) * 2;
            CP16(d0, Ahi + g0); CP16(d1, Ahi + g1);
            CP16(d0 + SH_A1 * 2 - SH_A0 * 2, Alo + g0);
            CP16(d1 + SH_A1 * 2 - SH_A0 * 2, Alo + g1);
        }
        // B hi/lo
        {
            size_t g0 = (size_t)(k0 + br0) * N + bx * 128 + bc0;
            size_t g1 = (size_t)(k0 + br1) * N + bx * 128 + bc1;
            uint32_t d0 = s0 + (SH_B0 + br0 * 136 + bc0) * 2;
            uint32_t d1 = s0 + (SH_B0 + br1 * 136 + bc1) * 2;
            CP16(d0, Bhi + g0); CP16(d1, Bhi + g1);
            CP16(d0 + (SH_B1 - SH_B0) * 2, Blo + g0);
            CP16(d1 + (SH_B1 - SH_B0) * 2, Blo + g1);
        }
        CP_COMMIT();
    };

    int nch = K >> 5;
    load_stage(0, 0);
    for (int c = 0; c < nch; c++) {
        if (c + 1 < nch) { load_stage(c + 1, (c + 1) & 1); CP_WAIT1(); }
        else             { CP_WAIT0(); }
        __syncthreads();
        uint32_t s0 = sbase + (uint32_t)((c & 1) * SH_STG) * 2;
#pragma unroll
        for (int ks = 0; ks < 2; ks++) {
            uint32_t ah[2][4], al[2][4];
#pragma unroll
            for (int mt = 0; mt < 2; mt++) {
                int row = wm * 32 + mt * 16 + (lane & 15);
                int col = ks * 16 + (lane >> 4) * 8;
                uint32_t a = s0 + (uint32_t)(SH_A0 + row * 40 + col) * 2;
                ldsm4(ah[mt], a);
                ldsm4(al[mt], a + (SH_A1 - SH_A0) * 2);
            }
#pragma unroll
            for (int nt2 = 0; nt2 < 4; nt2++) {
                uint32_t bh[4], bl[4];
                int krow = ks * 16 + (lane & 15);
                int ncol = wn * 64 + nt2 * 16 + (lane >> 4) * 8;
                uint32_t a = s0 + (uint32_t)(SH_B0 + krow * 136 + ncol) * 2;
                ldsm4t(bh, a);
                ldsm4t(bl, a + (SH_B1 - SH_B0) * 2);
#pragma unroll
                for (int p = 0; p < 2; p++) {
                    int nt = nt2 * 2 + p;
#pragma unroll
                    for (int mt = 0; mt < 2; mt++) {
                        mma_bf16(acc[mt][nt], ah[mt], bh[2 * p], bh[2 * p + 1]);
                        mma_bf16(acc[mt][nt], ah[mt], bl[2 * p], bl[2 * p + 1]);
                        mma_bf16(acc[mt][nt], al[mt], bh[2 * p], bh[2 * p + 1]);
                    }
                }
            }
        }
        __syncthreads();
    }

    // epilogue
#pragma unroll
    for (int mt = 0; mt < 2; mt++) {
#pragma unroll
        for (int nt = 0; nt < 8; nt++) {
            int r  = by * 128 + wm * 32 + mt * 16 + (lane >> 2);
            int cc = bx * 128 + wn * 64 + nt * 8 + (lane & 3) * 2;
            *(float2*)&C[(size_t)r * N + cc] =
                make_float2(acc[mt][nt][0], acc[mt][nt][1]);
            *(float2*)&C[(size_t)(r + 8) * N + cc] =
                make_float2(acc[mt][nt][2], acc[mt][nt][3]);
        }
    }
}

// ---------------- T5 bidirectional relative bucket ----------------
__device__ __forceinline__ int rel_bucket(int rp) {
    int rb = (rp > 0) ? (NBUCK / 2) : 0;
    int a  = rp < 0 ? -rp : rp;
    if (a < 8) return rb + a;
    float rf = (float)a;
    int large = 8 + (int)(logf(rf * 0.125f) * (8.0f / 2.772588722239781f));
    if (large > 15) large = 15;
    return rb + large;
}

// ---------------- block ids / global segments ----------------
__global__ void k_block_ids(const int* __restrict__ mask) {
    int b = blockIdx.x;
    __shared__ int s_cnt, s_max;
    if (threadIdx.x == 0) { s_cnt = 0; s_max = -1; }
    __syncthreads();
    int lc = 0;
    for (int i = threadIdx.x; i < SS; i += blockDim.x)
        if (((i & (GG - 1)) == GG - 1) && mask[b * SS + i] != 0) lc++;
    atomicAdd(&s_cnt, lc);
    __syncthreads();
    int full = s_cnt - 1;
    int lm = -1;
    for (int i = threadIdx.x; i < SS; i += blockDim.x) {
        int id;
        if (mask[b * SS + i] != 0) { id = i / GG; if (id > full) id = full; }
        else id = -1;
        g_bid[b * SS + i] = id;
        if (id > lm) lm = id;
    }
    atomicMax(&s_max, lm);
    __syncthreads();
    for (int g = threadIdx.x; g < GLL; g += blockDim.x)
        g_gseg[b * GLL + g] = (g <= s_max) ? 1 : 0;
}

// ---------------- global aggregates + RMSNorm ----------------
__global__ void k_global_agg(const float* __restrict__ hs, const float* __restrict__ gln_w) {
    int g = blockIdx.x, b = blockIdx.y;
    int t = threadIdx.x;
    float acc0 = 0.f, acc1 = 0.f, acc2 = 0.f, acc3 = 0.f;
#pragma unroll 1
    for (int s = 0; s < SS; s++) {
        if (g_bid[b * SS + s] == g) {
            const float* row = hs + ((size_t)(b * SS + s)) * DD;
            acc0 += row[t];
            acc1 += row[t + 256];
            acc2 += row[t + 512];
            acc3 += row[t + 768];
        }
    }
    __shared__ float red[256];
    red[t] = acc0 * acc0 + acc1 * acc1 + acc2 * acc2 + acc3 * acc3;
    __syncthreads();
    for (int off = 128; off > 0; off >>= 1) {
        if (t < off) red[t] += red[t + off];
        __syncthreads();
    }
    float var = red[0] * (1.0f / (float)DD);
    float sc = rsqrtf(var + 1e-6f);
    float* out = g_gi + ((size_t)(b * GLL + g)) * DD;
    out[t]       = acc0 * sc * gln_w[t];
    out[t + 256] = acc1 * sc * gln_w[t + 256];
    out[t + 512] = acc2 * sc * gln_w[t + 512];
    out[t + 768] = acc3 * sc * gln_w[t + 768];
}

// ---------------- bias tables ----------------
__global__ void k_localbias(const float* __restrict__ rel_bias) {
    int idx = blockIdx.x * blockDim.x + threadIdx.x;
    if (idx >= HH * BLL * 3 * BLL) return;
    int h  = idx / (BLL * 3 * BLL);
    int r  = idx % (BLL * 3 * BLL);
    int qi = r / (3 * BLL);
    int j  = r % (3 * BLL);
    int rel = j - BLL - qi;
    float v = rel_bias[rel_bucket(rel) * HH + h];
    if (!(rel > -BLL && rel < BLL)) v += NEGV;
    g_lbias[idx] = v;
}

__global__ void k_sidebias(const float* __restrict__ grel) {
    int idx = blockIdx.x * blockDim.x + threadIdx.x;
    if (idx >= HH * 257 * GLL) return;
    int h    = idx / (257 * GLL);
    int r    = idx % (257 * GLL);
    int bidp = r / GLL;
    int g    = r % GLL;
    int srp  = g - (bidp - 1);
    g_sbias[idx] = grel[rel_bucket(srp) * HH + h];
}

// ---------------- attention (unchanged) ----------------
#define CHUNK 16
#define NKEY  (3 * BLL + GLL)

__global__ __launch_bounds__(128)
void k_attn(const int* __restrict__ mask) {
    int h = blockIdx.x;
    int n = blockIdx.y;
    int b = blockIdx.z;
    int qi = threadIdx.x;
    int sq = n * BLL + qi;

    float4 q4[16];
    const float4* qsrc = (const float4*)(g_q + ((size_t)(b * SS + sq)) * DD + h * DKK);
#pragma unroll
    for (int i = 0; i < 16; i++) q4[i] = qsrc[i];

    int maskq = mask[b * SS + sq];
    int bidq  = g_bid[b * SS + sq];
    const float* ltab = g_lbias + ((size_t)(h * BLL + qi)) * (3 * BLL);
    const float* stab = g_sbias + ((size_t)(h * 257 + (bidq + 1))) * GLL;

    __shared__ float ks[CHUNK][DKK];
    __shared__ float vs[CHUNK][DKK];

    float4 acc4[16];
#pragma unroll
    for (int i = 0; i < 16; i++) acc4[i] = make_float4(0.f, 0.f, 0.f, 0.f);
    float m = -1e30f, l = 0.f;

    int lrow = threadIdx.x >> 3;
    int lcol = (threadIdx.x & 7) * 8;

    for (int c = 0; c < NKEY / CHUNK; c++) {
        int j0 = c * CHUNK;
        {
            int j = j0 + lrow;
            const float *ksrc = nullptr, *vsrc = nullptr;
            bool valid;
            if (j < 3 * BLL) {
                int t = (n - 1) * BLL + j;
                valid = (t >= 0) && (t < SS);
                if (valid) {
                    size_t off = ((size_t)(b * SS + t)) * DD + h * DKK + lcol;
                    ksrc = g_k + off; vsrc = g_v + off;
                }
            } else {
                int gI = j - 3 * BLL;
                valid = true;
                size_t off = ((size_t)(b * GLL + gI)) * DD + h * DKK + lcol;
                ksrc = g_sk + off; vsrc = g_sv + off;
            }
            float4 k0v, k1v, v0v, v1v;
            if (valid) {
                k0v = *(const float4*)(ksrc);     k1v = *(const float4*)(ksrc + 4);
                v0v = *(const float4*)(vsrc);     v1v = *(const float4*)(vsrc + 4);
            } else {
                k0v = k1v = v0v = v1v = make_float4(0.f, 0.f, 0.f, 0.f);
            }
            *(float4*)&ks[lrow][lcol]     = k0v;
            *(float4*)&ks[lrow][lcol + 4] = k1v;
            *(float4*)&vs[lrow][lcol]     = v0v;
            *(float4*)&vs[lrow][lcol + 4] = v1v;
        }
        __syncthreads();

        float sc[CHUNK];
#pragma unroll
        for (int j2 = 0; j2 < CHUNK; j2++) {
            int j = j0 + j2;
            const float4* kr = (const float4*)ks[j2];
            float s = 0.f;
#pragma unroll
            for (int i = 0; i < 16; i++) {
                float4 kk = kr[i];
                s += q4[i].x * kk.x + q4[i].y * kk.y + q4[i].z * kk.z + q4[i].w * kk.w;
            }
            float bias;
            if (j < 3 * BLL) {
                int t = (n - 1) * BLL + j;
                bias = ltab[j];
                bool ok = (t >= 0) && (t < SS);
                if (ok) ok = (mask[b * SS + t] != 0);
                ok = ok && (maskq != 0);
                if (!ok) bias += NEGV;
            } else {
                int gI = j - 3 * BLL;
                bias = stab[gI];
                if (maskq != g_gseg[b * GLL + gI]) bias += NEGV;
            }
            sc[j2] = s + bias;
        }

        float cm = sc[0];
#pragma unroll
        for (int j2 = 1; j2 < CHUNK; j2++) cm = fmaxf(cm, sc[j2]);
        float nm = fmaxf(m, cm);
        float rs = __expf(m - nm);
        l *= rs;
#pragma unroll
        for (int i = 0; i < 16; i++) {
            acc4[i].x *= rs; acc4[i].y *= rs; acc4[i].z *= rs; acc4[i].w *= rs;
        }
#pragma unroll
        for (int j2 = 0; j2 < CHUNK; j2++) {
            float p = __expf(sc[j2] - nm);
            l += p;
            const float4* vr = (const float4*)vs[j2];
#pragma unroll
            for (int i = 0; i < 16; i++) {
                float4 vv = vr[i];
                acc4[i].x += p * vv.x; acc4[i].y += p * vv.y;
                acc4[i].z += p * vv.z; acc4[i].w += p * vv.w;
            }
        }
        m = nm;
        __syncthreads();
    }

    float inv = 1.0f / l;
    float4* out = (float4*)(g_ctx + ((size_t)(b * SS + sq)) * DD + h * DKK);
#pragma unroll
    for (int i = 0; i < 16; i++) {
        float4 o = acc4[i];
        o.x *= inv; o.y *= inv; o.z *= inv; o.w *= inv;
        out[i] = o;
    }
}

// ---------------- launch ----------------
extern "C" void kernel_launch(void* const* d_in, const int* in_sizes, int n_in,
                              void* d_out, int out_size) {
    const float* hs   = (const float*)d_in[0];
    const float* Wq   = (const float*)d_in[1];
    const float* Wk   = (const float*)d_in[2];
    const float* Wv   = (const float*)d_in[3];
    const float* Wo   = (const float*)d_in[4];
    const float* relb = (const float*)d_in[5];
    const float* grel = (const float*)d_in[6];
    const float* gln  = (const float*)d_in[7];
    const int*   mask = (const int*)d_in[8];
    float* out = (float*)d_out;

    float* p_q;   cudaGetSymbolAddress((void**)&p_q,   g_q);
    float* p_k;   cudaGetSymbolAddress((void**)&p_k,   g_k);
    float* p_v;   cudaGetSymbolAddress((void**)&p_v,   g_v);
    float* p_ctx; cudaGetSymbolAddress((void**)&p_ctx, g_ctx);
    float* p_gi;  cudaGetSymbolAddress((void**)&p_gi,  g_gi);
    float* p_sk;  cudaGetSymbolAddress((void**)&p_sk,  g_sk);
    float* p_sv;  cudaGetSymbolAddress((void**)&p_sv,  g_sv);

    __nv_bfloat16 *hs_hi, *hs_lo, *ctx_hi, *ctx_lo, *gi_hi, *gi_lo, *w_hi, *w_lo;
    cudaGetSymbolAddress((void**)&hs_hi,  g_hs_hi);
    cudaGetSymbolAddress((void**)&hs_lo,  g_hs_lo);
    cudaGetSymbolAddress((void**)&ctx_hi, g_ctx_hi);
    cudaGetSymbolAddress((void**)&ctx_lo, g_ctx_lo);
    cudaGetSymbolAddress((void**)&gi_hi,  g_gi_hi);
    cudaGetSymbolAddress((void**)&gi_lo,  g_gi_lo);
    cudaGetSymbolAddress((void**)&w_hi,   g_w_hi);
    cudaGetSymbolAddress((void**)&w_lo,   g_w_lo);

    cudaFuncSetAttribute(bgemm, cudaFuncAttributeMaxDynamicSharedMemorySize, BGE_SMEM_BYTES);

    k_block_ids<<<BB, 256>>>(mask);
    k_global_agg<<<dim3(GLL, BB), 256>>>(hs, gln);

    {
        int n1 = HH * BLL * 3 * BLL;
        k_localbias<<<(n1 + 255) / 256, 256>>>(relb);
        int n2 = HH * 257 * GLL;
        k_sidebias<<<(n2 + 255) / 256, 256>>>(grel);
    }

    // hi/lo splits
    const int NHS = BB * SS * DD / 4;
    const int NW  = DD * DD / 4;
    const int NGI = BB * GLL * DD / 4;
    k_split<<<(NHS + 255) / 256, 256>>>((const float4*)hs, (uint2*)hs_hi, (uint2*)hs_lo, NHS);
    k_split<<<(NW + 255) / 256, 256>>>((const float4*)Wq, (uint2*)(w_hi + 0 * DD * DD), (uint2*)(w_lo + 0 * DD * DD), NW);
    k_split<<<(NW + 255) / 256, 256>>>((const float4*)Wk, (uint2*)(w_hi + 1 * DD * DD), (uint2*)(w_lo + 1 * DD * DD), NW);
    k_split<<<(NW + 255) / 256, 256>>>((const float4*)Wv, (uint2*)(w_hi + 2 * DD * DD), (uint2*)(w_lo + 2 * DD * DD), NW);
    k_split<<<(NW + 255) / 256, 256>>>((const float4*)Wo, (uint2*)(w_hi + 3 * DD * DD), (uint2*)(w_lo + 3 * DD * DD), NW);
    k_split<<<(NGI + 255) / 256, 256>>>((const float4*)p_gi, (uint2*)gi_hi, (uint2*)gi_lo, NGI);

    dim3 gBig(DD / 128, (BB * SS) / 128);   // (8, 64)
    dim3 gSm(DD / 128, (BB * GLL) / 128);   // (8, 4)
    bgemm<<<gBig, 256, BGE_SMEM_BYTES>>>(hs_hi, hs_lo, w_hi + 0 * DD * DD, w_lo + 0 * DD * DD, p_q, BB * SS, DD, DD);
    bgemm<<<gBig, 256, BGE_SMEM_BYTES>>>(hs_hi, hs_lo, w_hi + 1 * DD * DD, w_lo + 1 * DD * DD, p_k, BB * SS, DD, DD);
    bgemm<<<gBig, 256, BGE_SMEM_BYTES>>>(hs_hi, hs_lo, w_hi + 2 * DD * DD, w_lo + 2 * DD * DD, p_v, BB * SS, DD, DD);
    bgemm<<<gSm, 256, BGE_SMEM_BYTES>>>(gi_hi, gi_lo, w_hi + 1 * DD * DD, w_lo + 1 * DD * DD, p_sk, BB * GLL, DD, DD);
    bgemm<<<gSm, 256, BGE_SMEM_BYTES>>>(gi_hi, gi_lo, w_hi + 2 * DD * DD, w_lo + 2 * DD * DD, p_sv, BB * GLL, DD, DD);

    k_attn<<<dim3(HH, SS / BLL, BB), 128>>>(mask);

    k_split<<<(NHS + 255) / 256, 256>>>((const float4*)p_ctx, (uint2*)ctx_hi, (uint2*)ctx_lo, NHS);
    bgemm<<<gBig, 256, BGE_SMEM_BYTES>>>(ctx_hi, ctx_lo, w_hi + 3 * DD * DD, w_lo + 3 * DD * DD, out, BB * SS, DD, DD);
}

// round 6
// speedup vs baseline: 1.8009x; 1.2537x over previous
#include <cuda_runtime.h>
#include <cuda_bf16.h>
#include <cstdint>
#include <math.h>

#define BB   2
#define SS   4096
#define DD   1024
#define HH   16
#define DKK  64
#define BLL  128
#define GG   16
#define GLL  256
#define NBUCK 32
#define NEGV (-1e10f)

// ---------------- scratch (device globals: allocation-free) ----------------
__device__ float g_qkv[BB*SS*3*DD];    // [row][q|k|v]
__device__ float g_skv[BB*GLL*2*DD];   // [row][sk|sv]
__device__ float g_ctx[BB*SS*DD];
__device__ float g_gi [BB*GLL*DD];
__device__ float g_lbias[HH*BLL*3*BLL];
__device__ float g_sbias[HH*257*GLL];
__device__ int   g_bid [BB*SS];
__device__ int   g_gseg[BB*GLL];
__device__ int   g_full[BB];

// bf16 hi/lo split buffers
__device__ __nv_bfloat16 g_hs_hi  [BB*SS*DD];
__device__ __nv_bfloat16 g_hs_lo  [BB*SS*DD];
__device__ __nv_bfloat16 g_ctx_hi [BB*SS*DD];
__device__ __nv_bfloat16 g_ctx_lo [BB*SS*DD];
__device__ __nv_bfloat16 g_gi_hi  [BB*GLL*DD];
__device__ __nv_bfloat16 g_gi_lo  [BB*GLL*DD];
__device__ __nv_bfloat16 g_wqkv_hi[DD*3*DD];   // [k][3*DD] interleaved q|k|v cols
__device__ __nv_bfloat16 g_wqkv_lo[DD*3*DD];
__device__ __nv_bfloat16 g_wo_hi  [DD*DD];
__device__ __nv_bfloat16 g_wo_lo  [DD*DD];

// ---------------- helpers ----------------
__device__ __forceinline__ uint32_t smem_u32(const void* p) {
    uint32_t a;
    asm("{ .reg .u64 t; cvta.to.shared.u64 t, %1; cvt.u32.u64 %0, t; }" : "=r"(a) : "l"(p));
    return a;
}

#define CP16(dst, src) asm volatile("cp.async.cg.shared.global [%0], [%1], 16;" :: "r"(dst), "l"(src) : "memory")
#define CP_COMMIT()    asm volatile("cp.async.commit_group;" ::: "memory")
#define CP_WAIT1()     asm volatile("cp.async.wait_group 1;" ::: "memory")
#define CP_WAIT0()     asm volatile("cp.async.wait_group 0;" ::: "memory")

__device__ __forceinline__ void ldsm4(uint32_t* r, uint32_t a) {
    asm volatile("ldmatrix.sync.aligned.m8n8.x4.shared.b16 {%0,%1,%2,%3}, [%4];"
        : "=r"(r[0]), "=r"(r[1]), "=r"(r[2]), "=r"(r[3]) : "r"(a));
}
__device__ __forceinline__ void ldsm4t(uint32_t* r, uint32_t a) {
    asm volatile("ldmatrix.sync.aligned.m8n8.x4.trans.shared.b16 {%0,%1,%2,%3}, [%4];"
        : "=r"(r[0]), "=r"(r[1]), "=r"(r[2]), "=r"(r[3]) : "r"(a));
}
__device__ __forceinline__ void mma_bf16(float* d, const uint32_t* a, uint32_t b0, uint32_t b1) {
    asm volatile("mma.sync.aligned.m16n8k16.row.col.f32.bf16.bf16.f32 "
        "{%0,%1,%2,%3}, {%4,%5,%6,%7}, {%8,%9}, {%0,%1,%2,%3};"
        : "+f"(d[0]), "+f"(d[1]), "+f"(d[2]), "+f"(d[3])
        : "r"(a[0]), "r"(a[1]), "r"(a[2]), "r"(a[3]), "r"(b0), "r"(b1));
}

__device__ __forceinline__ void split4(float4 a, uint2& h, uint2& l) {
    __nv_bfloat162 h01 = __floats2bfloat162_rn(a.x, a.y);
    __nv_bfloat162 h23 = __floats2bfloat162_rn(a.z, a.w);
    float l0 = a.x - __bfloat162float(h01.x);
    float l1 = a.y - __bfloat162float(h01.y);
    float l2 = a.z - __bfloat162float(h23.x);
    float l3 = a.w - __bfloat162float(h23.y);
    __nv_bfloat162 q01 = __floats2bfloat162_rn(l0, l1);
    __nv_bfloat162 q23 = __floats2bfloat162_rn(l2, l3);
    h = make_uint2(*(uint32_t*)&h01, *(uint32_t*)&h23);
    l = make_uint2(*(uint32_t*)&q01, *(uint32_t*)&q23);
}

// ---------------- fp32 -> bf16 hi/lo split (plain layout) ----------------
__global__ void k_split(const float4* __restrict__ src,
                        uint2* __restrict__ hi, uint2* __restrict__ lo, int n4) {
    int i = blockIdx.x * 256 + threadIdx.x;
    if (i >= n4) return;
    uint2 h, l;
    split4(src[i], h, l);
    hi[i] = h; lo[i] = l;
}

// ---- weight split: 3 sources -> interleaved [k][3*DD] layout --------------
__global__ void k_split_qkv(const float4* __restrict__ Wq, const float4* __restrict__ Wk,
                            const float4* __restrict__ Wv,
                            uint2* __restrict__ hi, uint2* __restrict__ lo) {
    const int NW4 = DD * DD / 4;
    int idx = blockIdx.x * 256 + threadIdx.x;
    if (idx >= 3 * NW4) return;
    int i = idx / NW4;
    int r = idx % NW4;
    int k  = r >> 8;          // DD/4 = 256 float4 per row
    int n4 = r & 255;
    const float4* src = (i == 0) ? Wq : (i == 1) ? Wk : Wv;
    uint2 h, l;
    split4(src[r], h, l);
    int d = k * (3 * DD / 4) + i * (DD / 4) + n4;
    hi[d] = h; lo[d] = l;
}

// ============ bf16-split GEMM: C = A[.,K](lda) @ B[K,.](ldb), strides in elems
#define SH_A0   0
#define SH_A1   5120
#define SH_B0   10240
#define SH_B1   14592
#define SH_STG  18944
#define BGE_SMEM_BYTES (2 * SH_STG * 2)

__global__ __launch_bounds__(256, 1)
void bgemm(const __nv_bfloat16* __restrict__ Ahi, const __nv_bfloat16* __restrict__ Alo, int lda,
           const __nv_bfloat16* __restrict__ Bhi, const __nv_bfloat16* __restrict__ Blo, int ldb,
           float* __restrict__ C, int ldc, int K) {
    extern __shared__ __nv_bfloat16 sh[];
    uint32_t sbase = smem_u32(sh);

    int tid = threadIdx.x;
    int wid = tid >> 5, lane = tid & 31;
    int wm = wid & 3, wn = wid >> 2;
    int bx = blockIdx.x, by = blockIdx.y;

    float acc[2][8][4];
#pragma unroll
    for (int mt = 0; mt < 2; mt++)
#pragma unroll
        for (int nt = 0; nt < 8; nt++)
#pragma unroll
            for (int j = 0; j < 4; j++) acc[mt][nt][j] = 0.f;

    int ar0 = tid >> 2,          ac0 = (tid & 3) * 8;
    int ar1 = (tid + 256) >> 2,  ac1 = ((tid + 256) & 3) * 8;
    int br0 = tid >> 4,          bc0 = (tid & 15) * 8;
    int br1 = (tid + 256) >> 4,  bc1 = ((tid + 256) & 15) * 8;

    auto load_stage = [&](int c, int stage) {
        int k0 = c * 32;
        uint32_t s0 = sbase + (uint32_t)(stage * SH_STG) * 2;
        {
            size_t ga0 = (size_t)(by * 128 + ar0) * lda + k0 + ac0;
            size_t ga1 = (size_t)(by * 128 + ar1) * lda + k0 + ac1;
            uint32_t d0 = s0 + (SH_A0 + ar0 * 40 + ac0) * 2;
            uint32_t d1 = s0 + (SH_A0 + ar1 * 40 + ac1) * 2;
            CP16(d0, Ahi + ga0); CP16(d1, Ahi + ga1);
            CP16(d0 + (SH_A1 - SH_A0) * 2, Alo + ga0);
            CP16(d1 + (SH_A1 - SH_A0) * 2, Alo + ga1);
        }
        {
            size_t gb0 = (size_t)(k0 + br0) * ldb + bx * 128 + bc0;
            size_t gb1 = (size_t)(k0 + br1) * ldb + bx * 128 + bc1;
            uint32_t d0 = s0 + (SH_B0 + br0 * 136 + bc0) * 2;
            uint32_t d1 = s0 + (SH_B0 + br1 * 136 + bc1) * 2;
            CP16(d0, Bhi + gb0); CP16(d1, Bhi + gb1);
            CP16(d0 + (SH_B1 - SH_B0) * 2, Blo + gb0);
            CP16(d1 + (SH_B1 - SH_B0) * 2, Blo + gb1);
        }
        CP_COMMIT();
    };

    int nch = K >> 5;
    load_stage(0, 0);
    for (int c = 0; c < nch; c++) {
        if (c + 1 < nch) { load_stage(c + 1, (c + 1) & 1); CP_WAIT1(); }
        else             { CP_WAIT0(); }
        __syncthreads();
        uint32_t s0 = sbase + (uint32_t)((c & 1) * SH_STG) * 2;
#pragma unroll
        for (int ks = 0; ks < 2; ks++) {
            uint32_t ah[2][4], al[2][4];
#pragma unroll
            for (int mt = 0; mt < 2; mt++) {
                int row = wm * 32 + mt * 16 + (lane & 15);
                int col = ks * 16 + (lane >> 4) * 8;
                uint32_t a = s0 + (uint32_t)(SH_A0 + row * 40 + col) * 2;
                ldsm4(ah[mt], a);
                ldsm4(al[mt], a + (SH_A1 - SH_A0) * 2);
            }
#pragma unroll
            for (int nt2 = 0; nt2 < 4; nt2++) {
                uint32_t bh[4], bl[4];
                int krow = ks * 16 + (lane & 15);
                int ncol = wn * 64 + nt2 * 16 + (lane >> 4) * 8;
                uint32_t a = s0 + (uint32_t)(SH_B0 + krow * 136 + ncol) * 2;
                ldsm4t(bh, a);
                ldsm4t(bl, a + (SH_B1 - SH_B0) * 2);
#pragma unroll
                for (int p = 0; p < 2; p++) {
                    int nt = nt2 * 2 + p;
#pragma unroll
                    for (int mt = 0; mt < 2; mt++) {
                        mma_bf16(acc[mt][nt], ah[mt], bh[2 * p], bh[2 * p + 1]);
                        mma_bf16(acc[mt][nt], ah[mt], bl[2 * p], bl[2 * p + 1]);
                        mma_bf16(acc[mt][nt], al[mt], bh[2 * p], bh[2 * p + 1]);
                    }
                }
            }
        }
        __syncthreads();
    }

#pragma unroll
    for (int mt = 0; mt < 2; mt++) {
#pragma unroll
        for (int nt = 0; nt < 8; nt++) {
            int r  = by * 128 + wm * 32 + mt * 16 + (lane >> 2);
            int cc = bx * 128 + wn * 64 + nt * 8 + (lane & 3) * 2;
            *(float2*)&C[(size_t)r * ldc + cc] =
                make_float2(acc[mt][nt][0], acc[mt][nt][1]);
            *(float2*)&C[(size_t)(r + 8) * ldc + cc] =
                make_float2(acc[mt][nt][2], acc[mt][nt][3]);
        }
    }
}

// ---------------- T5 bidirectional relative bucket ----------------
__device__ __forceinline__ int rel_bucket(int rp) {
    int rb = (rp > 0) ? (NBUCK / 2) : 0;
    int a  = rp < 0 ? -rp : rp;
    if (a < 8) return rb + a;
    float rf = (float)a;
    int large = 8 + (int)(logf(rf * 0.125f) * (8.0f / 2.772588722239781f));
    if (large > 15) large = 15;
    return rb + large;
}

// ---------------- block ids / global segments ----------------
__global__ void k_block_ids(const int* __restrict__ mask) {
    int b = blockIdx.x;
    __shared__ int s_cnt, s_max;
    if (threadIdx.x == 0) { s_cnt = 0; s_max = -1; }
    __syncthreads();
    int lc = 0;
    for (int i = threadIdx.x; i < SS; i += blockDim.x)
        if (((i & (GG - 1)) == GG - 1) && mask[b * SS + i] != 0) lc++;
    atomicAdd(&s_cnt, lc);
    __syncthreads();
    int full = s_cnt - 1;
    int lm = -1;
    for (int i = threadIdx.x; i < SS; i += blockDim.x) {
        int id;
        if (mask[b * SS + i] != 0) { id = i / GG; if (id > full) id = full; }
        else id = -1;
        g_bid[b * SS + i] = id;
        if (id > lm) lm = id;
    }
    atomicMax(&s_max, lm);
    __syncthreads();
    for (int g = threadIdx.x; g < GLL; g += blockDim.x)
        g_gseg[b * GLL + g] = (g <= s_max) ? 1 : 0;
    if (threadIdx.x == 0) g_full[b] = full;
}

// ---------------- global aggregates + RMSNorm (range-restricted) ----------------
__global__ void k_global_agg(const float* __restrict__ hs, const float* __restrict__ gln_w) {
    int g = blockIdx.x, b = blockIdx.y;
    int t = threadIdx.x;
    int full = g_full[b];
    float acc0 = 0.f, acc1 = 0.f, acc2 = 0.f, acc3 = 0.f;
    if (g <= full) {
        int s_begin = g * GG;
        int s_end   = (g == full) ? SS : (g + 1) * GG;
#pragma unroll 1
        for (int s = s_begin; s < s_end; s++) {
            if (g_bid[b * SS + s] == g) {
                const float* row = hs + ((size_t)(b * SS + s)) * DD;
                acc0 += row[t];
                acc1 += row[t + 256];
                acc2 += row[t + 512];
                acc3 += row[t + 768];
            }
        }
    }
    __shared__ float red[256];
    red[t] = acc0 * acc0 + acc1 * acc1 + acc2 * acc2 + acc3 * acc3;
    __syncthreads();
    for (int off = 128; off > 0; off >>= 1) {
        if (t < off) red[t] += red[t + off];
        __syncthreads();
    }
    float var = red[0] * (1.0f / (float)DD);
    float sc = rsqrtf(var + 1e-6f);
    float* out = g_gi + ((size_t)(b * GLL + g)) * DD;
    out[t]       = acc0 * sc * gln_w[t];
    out[t + 256] = acc1 * sc * gln_w[t + 256];
    out[t + 512] = acc2 * sc * gln_w[t + 512];
    out[t + 768] = acc3 * sc * gln_w[t + 768];
}

// ---------------- bias tables ----------------
__global__ void k_localbias(const float* __restrict__ rel_bias) {
    int idx = blockIdx.x * blockDim.x + threadIdx.x;
    if (idx >= HH * BLL * 3 * BLL) return;
    int h  = idx / (BLL * 3 * BLL);
    int r  = idx % (BLL * 3 * BLL);
    int qi = r / (3 * BLL);
    int j  = r % (3 * BLL);
    int rel = j - BLL - qi;
    float v = rel_bias[rel_bucket(rel) * HH + h];
    if (!(rel > -BLL && rel < BLL)) v += NEGV;
    g_lbias[idx] = v;
}

__global__ void k_sidebias(const float* __restrict__ grel) {
    int idx = blockIdx.x * blockDim.x + threadIdx.x;
    if (idx >= HH * 257 * GLL) return;
    int h    = idx / (257 * GLL);
    int r    = idx % (257 * GLL);
    int bidp = r / GLL;
    int g    = r % GLL;
    int srp  = g - (bidp - 1);
    g_sbias[idx] = grel[rel_bucket(srp) * HH + h];
}

// ---------------- attention ----------------
#define CHUNK 16
#define NKEY  (3 * BLL + GLL)

__global__ __launch_bounds__(128)
void k_attn(const int* __restrict__ mask) {
    int h = blockIdx.x;
    int n = blockIdx.y;
    int b = blockIdx.z;
    int qi = threadIdx.x;
    int sq = n * BLL + qi;

    float4 q4[16];
    const float4* qsrc = (const float4*)(g_qkv + ((size_t)(b * SS + sq)) * (3 * DD) + h * DKK);
#pragma unroll
    for (int i = 0; i < 16; i++) q4[i] = qsrc[i];

    int maskq = mask[b * SS + sq];
    int bidq  = g_bid[b * SS + sq];
    const float* ltab = g_lbias + ((size_t)(h * BLL + qi)) * (3 * BLL);
    const float* stab = g_sbias + ((size_t)(h * 257 + (bidq + 1))) * GLL;

    __shared__ float ks[CHUNK][DKK];
    __shared__ float vs[CHUNK][DKK];

    float4 acc4[16];
#pragma unroll
    for (int i = 0; i < 16; i++) acc4[i] = make_float4(0.f, 0.f, 0.f, 0.f);
    float m = -1e30f, l = 0.f;

    int lrow = threadIdx.x >> 3;
    int lcol = (threadIdx.x & 7) * 8;

    for (int c = 0; c < NKEY / CHUNK; c++) {
        int j0 = c * CHUNK;
        {
            int j = j0 + lrow;
            const float *ksrc = nullptr, *vsrc = nullptr;
            bool valid;
            if (j < 3 * BLL) {
                int t = (n - 1) * BLL + j;
                valid = (t >= 0) && (t < SS);
                if (valid) {
                    const float* base = g_qkv + ((size_t)(b * SS + t)) * (3 * DD) + h * DKK + lcol;
                    ksrc = base + DD; vsrc = base + 2 * DD;
                }
            } else {
                int gI = j - 3 * BLL;
                valid = true;
                const float* base = g_skv + ((size_t)(b * GLL + gI)) * (2 * DD) + h * DKK + lcol;
                ksrc = base; vsrc = base + DD;
            }
            float4 k0v, k1v, v0v, v1v;
            if (valid) {
                k0v = *(const float4*)(ksrc);     k1v = *(const float4*)(ksrc + 4);
                v0v = *(const float4*)(vsrc);     v1v = *(const float4*)(vsrc + 4);
            } else {
                k0v = k1v = v0v = v1v = make_float4(0.f, 0.f, 0.f, 0.f);
            }
            *(float4*)&ks[lrow][lcol]     = k0v;
            *(float4*)&ks[lrow][lcol + 4] = k1v;
            *(float4*)&vs[lrow][lcol]     = v0v;
            *(float4*)&vs[lrow][lcol + 4] = v1v;
        }
        __syncthreads();

        float sc[CHUNK];
#pragma unroll
        for (int j2 = 0; j2 < CHUNK; j2++) {
            int j = j0 + j2;
            const float4* kr = (const float4*)ks[j2];
            float s = 0.f;
#pragma unroll
            for (int i = 0; i < 16; i++) {
                float4 kk = kr[i];
                s += q4[i].x * kk.x + q4[i].y * kk.y + q4[i].z * kk.z + q4[i].w * kk.w;
            }
            float bias;
            if (j < 3 * BLL) {
                int t = (n - 1) * BLL + j;
                bias = ltab[j];
                bool ok = (t >= 0) && (t < SS);
                if (ok) ok = (mask[b * SS + t] != 0);
                ok = ok && (maskq != 0);
                if (!ok) bias += NEGV;
            } else {
                int gI = j - 3 * BLL;
                bias = stab[gI];
                if (maskq != g_gseg[b * GLL + gI]) bias += NEGV;
            }
            sc[j2] = s + bias;
        }

        float cm = sc[0];
#pragma unroll
        for (int j2 = 1; j2 < CHUNK; j2++) cm = fmaxf(cm, sc[j2]);
        float nm = fmaxf(m, cm);
        float rs = __expf(m - nm);
        l *= rs;
#pragma unroll
        for (int i = 0; i < 16; i++) {
            acc4[i].x *= rs; acc4[i].y *= rs; acc4[i].z *= rs; acc4[i].w *= rs;
        }
#pragma unroll
        for (int j2 = 0; j2 < CHUNK; j2++) {
            float p = __expf(sc[j2] - nm);
            l += p;
            const float4* vr = (const float4*)vs[j2];
#pragma unroll
            for (int i = 0; i < 16; i++) {
                float4 vv = vr[i];
                acc4[i].x += p * vv.x; acc4[i].y += p * vv.y;
                acc4[i].z += p * vv.z; acc4[i].w += p * vv.w;
            }
        }
        m = nm;
        __syncthreads();
    }

    float inv = 1.0f / l;
    float4* out = (float4*)(g_ctx + ((size_t)(b * SS + sq)) * DD + h * DKK);
#pragma unroll
    for (int i = 0; i < 16; i++) {
        float4 o = acc4[i];
        o.x *= inv; o.y *= inv; o.z *= inv; o.w *= inv;
        out[i] = o;
    }
}

// ---------------- launch ----------------
extern "C" void kernel_launch(void* const* d_in, const int* in_sizes, int n_in,
                              void* d_out, int out_size) {
    const float* hs   = (const float*)d_in[0];
    const float* Wq   = (const float*)d_in[1];
    const float* Wk   = (const float*)d_in[2];
    const float* Wv   = (const float*)d_in[3];
    const float* Wo   = (const float*)d_in[4];
    const float* relb = (const float*)d_in[5];
    const float* grel = (const float*)d_in[6];
    const float* gln  = (const float*)d_in[7];
    const int*   mask = (const int*)d_in[8];
    float* out = (float*)d_out;

    float *p_qkv, *p_skv, *p_ctx, *p_gi;
    cudaGetSymbolAddress((void**)&p_qkv, g_qkv);
    cudaGetSymbolAddress((void**)&p_skv, g_skv);
    cudaGetSymbolAddress((void**)&p_ctx, g_ctx);
    cudaGetSymbolAddress((void**)&p_gi,  g_gi);

    __nv_bfloat16 *hs_hi, *hs_lo, *ctx_hi, *ctx_lo, *gi_hi, *gi_lo;
    __nv_bfloat16 *wqkv_hi, *wqkv_lo, *wo_hi, *wo_lo;
    cudaGetSymbolAddress((void**)&hs_hi,   g_hs_hi);
    cudaGetSymbolAddress((void**)&hs_lo,   g_hs_lo);
    cudaGetSymbolAddress((void**)&ctx_hi,  g_ctx_hi);
    cudaGetSymbolAddress((void**)&ctx_lo,  g_ctx_lo);
    cudaGetSymbolAddress((void**)&gi_hi,   g_gi_hi);
    cudaGetSymbolAddress((void**)&gi_lo,   g_gi_lo);
    cudaGetSymbolAddress((void**)&wqkv_hi, g_wqkv_hi);
    cudaGetSymbolAddress((void**)&wqkv_lo, g_wqkv_lo);
    cudaGetSymbolAddress((void**)&wo_hi,   g_wo_hi);
    cudaGetSymbolAddress((void**)&wo_lo,   g_wo_lo);

    cudaFuncSetAttribute(bgemm, cudaFuncAttributeMaxDynamicSharedMemorySize, BGE_SMEM_BYTES);

    const int NHS4 = BB * SS * DD / 4;
    const int NW4  = DD * DD / 4;
    const int NGI4 = BB * GLL * DD / 4;

    // #1..#3: prerequisites for the big QKV GEMM
    k_split_qkv<<<(3 * NW4 + 255) / 256, 256>>>((const float4*)Wq, (const float4*)Wk,
                                                (const float4*)Wv, (uint2*)wqkv_hi, (uint2*)wqkv_lo);
    k_split<<<(NHS4 + 255) / 256, 256>>>((const float4*)hs, (uint2*)hs_hi, (uint2*)hs_lo, NHS4);
    k_block_ids<<<BB, 256>>>(mask);

    // #4: fused QKV GEMM (profiled slot)
    bgemm<<<dim3(3 * DD / 128, (BB * SS) / 128), 256, BGE_SMEM_BYTES>>>(
        hs_hi, hs_lo, DD, wqkv_hi, wqkv_lo, 3 * DD, p_qkv, 3 * DD, DD);

    // global path
    k_global_agg<<<dim3(GLL, BB), 256>>>(hs, gln);
    k_split<<<(NGI4 + 255) / 256, 256>>>((const float4*)p_gi, (uint2*)gi_hi, (uint2*)gi_lo, NGI4);
    bgemm<<<dim3(2 * DD / 128, (BB * GLL) / 128), 256, BGE_SMEM_BYTES>>>(
        gi_hi, gi_lo, DD, wqkv_hi + DD, wqkv_lo + DD, 3 * DD, p_skv, 2 * DD, DD);

    // bias tables + Wo split
    {
        int n1 = HH * BLL * 3 * BLL;
        k_localbias<<<(n1 + 255) / 256, 256>>>(relb);
        int n2 = HH * 257 * GLL;
        k_sidebias<<<(n2 + 255) / 256, 256>>>(grel);
    }
    k_split<<<(NW4 + 255) / 256, 256>>>((const float4*)Wo, (uint2*)wo_hi, (uint2*)wo_lo, NW4);

    // attention
    k_attn<<<dim3(HH, SS / BLL, BB), 128>>>(mask);

    // output projection
    k_split<<<(NHS4 + 255) / 256, 256>>>((const float4*)p_ctx, (uint2*)ctx_hi, (uint2*)ctx_lo, NHS4);
    bgemm<<<dim3(DD / 128, (BB * SS) / 128), 256, BGE_SMEM_BYTES>>>(
        ctx_hi, ctx_lo, DD, wo_hi, wo_lo, DD, out, DD, DD);
}

// round 7
// speedup vs baseline: 1.9532x; 1.0846x over previous
#include <cuda_runtime.h>
#include <cuda_bf16.h>
#include <cstdint>
#include <math.h>

#define BB   2
#define SS   4096
#define DD   1024
#define HH   16
#define DKK  64
#define BLL  128
#define GG   16
#define GLL  256
#define NBUCK 32
#define NEGV (-1e10f)

// ---------------- scratch (device globals: allocation-free) ----------------
__device__ float g_qkv[BB*SS*3*DD];    // [row][q|k|v]
__device__ float g_skv[BB*GLL*2*DD];   // [row][sk|sv]
__device__ float g_ctx[BB*SS*DD];
__device__ float g_gi [BB*GLL*DD];
__device__ float g_lbias[HH*BLL*3*BLL];
__device__ float g_sbias[HH*257*GLL];
__device__ int   g_bid [BB*SS];
__device__ int   g_gseg[BB*GLL];
__device__ int   g_full[BB];

// bf16 hi/lo split buffers
__device__ __nv_bfloat16 g_hs_hi  [BB*SS*DD];
__device__ __nv_bfloat16 g_hs_lo  [BB*SS*DD];
__device__ __nv_bfloat16 g_ctx_hi [BB*SS*DD];
__device__ __nv_bfloat16 g_ctx_lo [BB*SS*DD];
__device__ __nv_bfloat16 g_gi_hi  [BB*GLL*DD];
__device__ __nv_bfloat16 g_gi_lo  [BB*GLL*DD];
__device__ __nv_bfloat16 g_wqkv_hi[DD*3*DD];
__device__ __nv_bfloat16 g_wqkv_lo[DD*3*DD];
__device__ __nv_bfloat16 g_wo_hi  [DD*DD];
__device__ __nv_bfloat16 g_wo_lo  [DD*DD];

// ---------------- helpers ----------------
__device__ __forceinline__ uint32_t smem_u32(const void* p) {
    uint32_t a;
    asm("{ .reg .u64 t; cvta.to.shared.u64 t, %1; cvt.u32.u64 %0, t; }" : "=r"(a) : "l"(p));
    return a;
}

#define CP16(dst, src) asm volatile("cp.async.cg.shared.global [%0], [%1], 16;" :: "r"(dst), "l"(src) : "memory")
#define CP_COMMIT()    asm volatile("cp.async.commit_group;" ::: "memory")
#define CP_WAIT1()     asm volatile("cp.async.wait_group 1;" ::: "memory")
#define CP_WAIT0()     asm volatile("cp.async.wait_group 0;" ::: "memory")

__device__ __forceinline__ void ldsm4(uint32_t* r, uint32_t a) {
    asm volatile("ldmatrix.sync.aligned.m8n8.x4.shared.b16 {%0,%1,%2,%3}, [%4];"
        : "=r"(r[0]), "=r"(r[1]), "=r"(r[2]), "=r"(r[3]) : "r"(a));
}
__device__ __forceinline__ void ldsm4t(uint32_t* r, uint32_t a) {
    asm volatile("ldmatrix.sync.aligned.m8n8.x4.trans.shared.b16 {%0,%1,%2,%3}, [%4];"
        : "=r"(r[0]), "=r"(r[1]), "=r"(r[2]), "=r"(r[3]) : "r"(a));
}
__device__ __forceinline__ void mma_bf16(float* d, const uint32_t* a, uint32_t b0, uint32_t b1) {
    asm volatile("mma.sync.aligned.m16n8k16.row.col.f32.bf16.bf16.f32 "
        "{%0,%1,%2,%3}, {%4,%5,%6,%7}, {%8,%9}, {%0,%1,%2,%3};"
        : "+f"(d[0]), "+f"(d[1]), "+f"(d[2]), "+f"(d[3])
        : "r"(a[0]), "r"(a[1]), "r"(a[2]), "r"(a[3]), "r"(b0), "r"(b1));
}

__device__ __forceinline__ void split4(float4 a, uint2& h, uint2& l) {
    __nv_bfloat162 h01 = __floats2bfloat162_rn(a.x, a.y);
    __nv_bfloat162 h23 = __floats2bfloat162_rn(a.z, a.w);
    float l0 = a.x - __bfloat162float(h01.x);
    float l1 = a.y - __bfloat162float(h01.y);
    float l2 = a.z - __bfloat162float(h23.x);
    float l3 = a.w - __bfloat162float(h23.y);
    __nv_bfloat162 q01 = __floats2bfloat162_rn(l0, l1);
    __nv_bfloat162 q23 = __floats2bfloat162_rn(l2, l3);
    h = make_uint2(*(uint32_t*)&h01, *(uint32_t*)&h23);
    l = make_uint2(*(uint32_t*)&q01, *(uint32_t*)&q23);
}

// ---------------- fp32 -> bf16 hi/lo split ----------------
__global__ void k_split(const float4* __restrict__ src,
                        uint2* __restrict__ hi, uint2* __restrict__ lo, int n4) {
    int i = blockIdx.x * 256 + threadIdx.x;
    if (i >= n4) return;
    uint2 h, l;
    split4(src[i], h, l);
    hi[i] = h; lo[i] = l;
}

// ---- weight split: 3 sources -> interleaved [k][3*DD] layout --------------
__global__ void k_split_qkv(const float4* __restrict__ Wq, const float4* __restrict__ Wk,
                            const float4* __restrict__ Wv,
                            uint2* __restrict__ hi, uint2* __restrict__ lo) {
    const int NW4 = DD * DD / 4;
    int idx = blockIdx.x * 256 + threadIdx.x;
    if (idx >= 3 * NW4) return;
    int i = idx / NW4;
    int r = idx % NW4;
    int k  = r >> 8;
    int n4 = r & 255;
    const float4* src = (i == 0) ? Wq : (i == 1) ? Wk : Wv;
    uint2 h, l;
    split4(src[r], h, l);
    int d = k * (3 * DD / 4) + i * (DD / 4) + n4;
    hi[d] = h; lo[d] = l;
}

// ============ bf16-split GEMM ============
#define SH_A0   0
#define SH_A1   5120
#define SH_B0   10240
#define SH_B1   14592
#define SH_STG  18944
#define BGE_SMEM_BYTES (2 * SH_STG * 2)

__global__ __launch_bounds__(256, 2)
void bgemm(const __nv_bfloat16* __restrict__ Ahi, const __nv_bfloat16* __restrict__ Alo, int lda,
           const __nv_bfloat16* __restrict__ Bhi, const __nv_bfloat16* __restrict__ Blo, int ldb,
           float* __restrict__ C, int ldc, int K) {
    extern __shared__ __nv_bfloat16 sh[];
    uint32_t sbase = smem_u32(sh);

    int tid = threadIdx.x;
    int wid = tid >> 5, lane = tid & 31;
    int wm = wid & 3, wn = wid >> 2;
    int bx = blockIdx.x, by = blockIdx.y;

    float acc[2][8][4];
#pragma unroll
    for (int mt = 0; mt < 2; mt++)
#pragma unroll
        for (int nt = 0; nt < 8; nt++)
#pragma unroll
            for (int j = 0; j < 4; j++) acc[mt][nt][j] = 0.f;

    int ar0 = tid >> 2,          ac0 = (tid & 3) * 8;
    int ar1 = (tid + 256) >> 2,  ac1 = ((tid + 256) & 3) * 8;
    int br0 = tid >> 4,          bc0 = (tid & 15) * 8;
    int br1 = (tid + 256) >> 4,  bc1 = ((tid + 256) & 15) * 8;

    auto load_stage = [&](int c, int stage) {
        int k0 = c * 32;
        uint32_t s0 = sbase + (uint32_t)(stage * SH_STG) * 2;
        {
            size_t ga0 = (size_t)(by * 128 + ar0) * lda + k0 + ac0;
            size_t ga1 = (size_t)(by * 128 + ar1) * lda + k0 + ac1;
            uint32_t d0 = s0 + (SH_A0 + ar0 * 40 + ac0) * 2;
            uint32_t d1 = s0 + (SH_A0 + ar1 * 40 + ac1) * 2;
            CP16(d0, Ahi + ga0); CP16(d1, Ahi + ga1);
            CP16(d0 + (SH_A1 - SH_A0) * 2, Alo + ga0);
            CP16(d1 + (SH_A1 - SH_A0) * 2, Alo + ga1);
        }
        {
            size_t gb0 = (size_t)(k0 + br0) * ldb + bx * 128 + bc0;
            size_t gb1 = (size_t)(k0 + br1) * ldb + bx * 128 + bc1;
            uint32_t d0 = s0 + (SH_B0 + br0 * 136 + bc0) * 2;
            uint32_t d1 = s0 + (SH_B0 + br1 * 136 + bc1) * 2;
            CP16(d0, Bhi + gb0); CP16(d1, Bhi + gb1);
            CP16(d0 + (SH_B1 - SH_B0) * 2, Blo + gb0);
            CP16(d1 + (SH_B1 - SH_B0) * 2, Blo + gb1);
        }
        CP_COMMIT();
    };

    int nch = K >> 5;
    load_stage(0, 0);
    for (int c = 0; c < nch; c++) {
        if (c + 1 < nch) { load_stage(c + 1, (c + 1) & 1); CP_WAIT1(); }
        else             { CP_WAIT0(); }
        __syncthreads();
        uint32_t s0 = sbase + (uint32_t)((c & 1) * SH_STG) * 2;
#pragma unroll
        for (int ks = 0; ks < 2; ks++) {
            uint32_t ah[2][4], al[2][4];
#pragma unroll
            for (int mt = 0; mt < 2; mt++) {
                int row = wm * 32 + mt * 16 + (lane & 15);
                int col = ks * 16 + (lane >> 4) * 8;
                uint32_t a = s0 + (uint32_t)(SH_A0 + row * 40 + col) * 2;
                ldsm4(ah[mt], a);
                ldsm4(al[mt], a + (SH_A1 - SH_A0) * 2);
            }
#pragma unroll
            for (int nt2 = 0; nt2 < 4; nt2++) {
                uint32_t bh[4], bl[4];
                int krow = ks * 16 + (lane & 15);
                int ncol = wn * 64 + nt2 * 16 + (lane >> 4) * 8;
                uint32_t a = s0 + (uint32_t)(SH_B0 + krow * 136 + ncol) * 2;
                ldsm4t(bh, a);
                ldsm4t(bl, a + (SH_B1 - SH_B0) * 2);
#pragma unroll
                for (int p = 0; p < 2; p++) {
                    int nt = nt2 * 2 + p;
#pragma unroll
                    for (int mt = 0; mt < 2; mt++) {
                        mma_bf16(acc[mt][nt], ah[mt], bh[2 * p], bh[2 * p + 1]);
                        mma_bf16(acc[mt][nt], ah[mt], bl[2 * p], bl[2 * p + 1]);
                        mma_bf16(acc[mt][nt], al[mt], bh[2 * p], bh[2 * p + 1]);
                    }
                }
            }
        }
        __syncthreads();
    }

#pragma unroll
    for (int mt = 0; mt < 2; mt++) {
#pragma unroll
        for (int nt = 0; nt < 8; nt++) {
            int r  = by * 128 + wm * 32 + mt * 16 + (lane >> 2);
            int cc = bx * 128 + wn * 64 + nt * 8 + (lane & 3) * 2;
            *(float2*)&C[(size_t)r * ldc + cc] =
                make_float2(acc[mt][nt][0], acc[mt][nt][1]);
            *(float2*)&C[(size_t)(r + 8) * ldc + cc] =
                make_float2(acc[mt][nt][2], acc[mt][nt][3]);
        }
    }
}

// ---------------- T5 bidirectional relative bucket ----------------
__device__ __forceinline__ int rel_bucket(int rp) {
    int rb = (rp > 0) ? (NBUCK / 2) : 0;
    int a  = rp < 0 ? -rp : rp;
    if (a < 8) return rb + a;
    float rf = (float)a;
    int large = 8 + (int)(logf(rf * 0.125f) * (8.0f / 2.772588722239781f));
    if (large > 15) large = 15;
    return rb + large;
}

// ---------------- block ids / global segments ----------------
__global__ void k_block_ids(const int* __restrict__ mask) {
    int b = blockIdx.x;
    __shared__ int s_cnt, s_max;
    if (threadIdx.x == 0) { s_cnt = 0; s_max = -1; }
    __syncthreads();
    int lc = 0;
    for (int i = threadIdx.x; i < SS; i += blockDim.x)
        if (((i & (GG - 1)) == GG - 1) && mask[b * SS + i] != 0) lc++;
    atomicAdd(&s_cnt, lc);
    __syncthreads();
    int full = s_cnt - 1;
    int lm = -1;
    for (int i = threadIdx.x; i < SS; i += blockDim.x) {
        int id;
        if (mask[b * SS + i] != 0) { id = i / GG; if (id > full) id = full; }
        else id = -1;
        g_bid[b * SS + i] = id;
        if (id > lm) lm = id;
    }
    atomicMax(&s_max, lm);
    __syncthreads();
    for (int g = threadIdx.x; g < GLL; g += blockDim.x)
        g_gseg[b * GLL + g] = (g <= s_max) ? 1 : 0;
    if (threadIdx.x == 0) g_full[b] = full;
}

// ---------------- global aggregates + RMSNorm ----------------
__global__ void k_global_agg(const float* __restrict__ hs, const float* __restrict__ gln_w) {
    int g = blockIdx.x, b = blockIdx.y;
    int t = threadIdx.x;
    int full = g_full[b];
    float acc0 = 0.f, acc1 = 0.f, acc2 = 0.f, acc3 = 0.f;
    if (g <= full) {
        int s_begin = g * GG;
        int s_end   = (g == full) ? SS : (g + 1) * GG;
#pragma unroll 1
        for (int s = s_begin; s < s_end; s++) {
            if (g_bid[b * SS + s] == g) {
                const float* row = hs + ((size_t)(b * SS + s)) * DD;
                acc0 += row[t];
                acc1 += row[t + 256];
                acc2 += row[t + 512];
                acc3 += row[t + 768];
            }
        }
    }
    __shared__ float red[256];
    red[t] = acc0 * acc0 + acc1 * acc1 + acc2 * acc2 + acc3 * acc3;
    __syncthreads();
    for (int off = 128; off > 0; off >>= 1) {
        if (t < off) red[t] += red[t + off];
        __syncthreads();
    }
    float var = red[0] * (1.0f / (float)DD);
    float sc = rsqrtf(var + 1e-6f);
    float* out = g_gi + ((size_t)(b * GLL + g)) * DD;
    out[t]       = acc0 * sc * gln_w[t];
    out[t + 256] = acc1 * sc * gln_w[t + 256];
    out[t + 512] = acc2 * sc * gln_w[t + 512];
    out[t + 768] = acc3 * sc * gln_w[t + 768];
}

// ---------------- bias tables ----------------
__global__ void k_localbias(const float* __restrict__ rel_bias) {
    int idx = blockIdx.x * blockDim.x + threadIdx.x;
    if (idx >= HH * BLL * 3 * BLL) return;
    int h  = idx / (BLL * 3 * BLL);
    int r  = idx % (BLL * 3 * BLL);
    int qi = r / (3 * BLL);
    int j  = r % (3 * BLL);
    int rel = j - BLL - qi;
    float v = rel_bias[rel_bucket(rel) * HH + h];
    if (!(rel > -BLL && rel < BLL)) v += NEGV;
    g_lbias[idx] = v;
}

__global__ void k_sidebias(const float* __restrict__ grel) {
    int idx = blockIdx.x * blockDim.x + threadIdx.x;
    if (idx >= HH * 257 * GLL) return;
    int h    = idx / (257 * GLL);
    int r    = idx % (257 * GLL);
    int bidp = r / GLL;
    int g    = r % GLL;
    int srp  = g - (bidp - 1);
    g_sbias[idx] = grel[rel_bucket(srp) * HH + h];
}

// ---------------- attention (double-buffered cp.async staging) ----------------
#define CHUNK 16
#define NKEY  (3 * BLL + GLL)
#define NCH   (NKEY / CHUNK)

__global__ __launch_bounds__(128)
void k_attn(const int* __restrict__ mask) {
    int h = blockIdx.x;
    int n = blockIdx.y;
    int b = blockIdx.z;
    int qi = threadIdx.x;
    int sq = n * BLL + qi;

    float4 q4[16];
    const float4* qsrc = (const float4*)(g_qkv + ((size_t)(b * SS + sq)) * (3 * DD) + h * DKK);
#pragma unroll
    for (int i = 0; i < 16; i++) q4[i] = qsrc[i];

    int maskq = mask[b * SS + sq];
    int bidq  = g_bid[b * SS + sq];
    const float* ltab = g_lbias + ((size_t)(h * BLL + qi)) * (3 * BLL);
    const float* stab = g_sbias + ((size_t)(h * 257 + (bidq + 1))) * GLL;

    __shared__ float ks[2][CHUNK][DKK];
    __shared__ float vs[2][CHUNK][DKK];

    float4 acc4[16];
#pragma unroll
    for (int i = 0; i < 16; i++) acc4[i] = make_float4(0.f, 0.f, 0.f, 0.f);
    float m = -1e30f, l = 0.f;

    int lrow = threadIdx.x >> 3;
    int lcol = (threadIdx.x & 7) * 8;

    auto stage = [&](int c, int buf) {
        int j = c * CHUNK + lrow;
        uint32_t dk = smem_u32(&ks[buf][lrow][lcol]);
        uint32_t dv = smem_u32(&vs[buf][lrow][lcol]);
        if (j < 3 * BLL) {
            int t = (n - 1) * BLL + j;
            if (t >= 0 && t < SS) {
                const float* base = g_qkv + ((size_t)(b * SS + t)) * (3 * DD) + h * DKK + lcol;
                CP16(dk, base + DD);      CP16(dk + 16, base + DD + 4);
                CP16(dv, base + 2 * DD);  CP16(dv + 16, base + 2 * DD + 4);
            } else {
                float4 z = make_float4(0.f, 0.f, 0.f, 0.f);
                *(float4*)&ks[buf][lrow][lcol]     = z;
                *(float4*)&ks[buf][lrow][lcol + 4] = z;
                *(float4*)&vs[buf][lrow][lcol]     = z;
                *(float4*)&vs[buf][lrow][lcol + 4] = z;
            }
        } else {
            int gI = j - 3 * BLL;
            const float* base = g_skv + ((size_t)(b * GLL + gI)) * (2 * DD) + h * DKK + lcol;
            CP16(dk, base);      CP16(dk + 16, base + 4);
            CP16(dv, base + DD); CP16(dv + 16, base + DD + 4);
        }
        CP_COMMIT();
    };

    stage(0, 0);
    for (int c = 0; c < NCH; c++) {
        int buf = c & 1;
        if (c + 1 < NCH) { stage(c + 1, (c + 1) & 1); CP_WAIT1(); }
        else             { CP_WAIT0(); }
        __syncthreads();

        int j0 = c * CHUNK;
        float sc[CHUNK];
#pragma unroll
        for (int j2 = 0; j2 < CHUNK; j2++) {
            int j = j0 + j2;
            const float4* kr = (const float4*)ks[buf][j2];
            float s = 0.f;
#pragma unroll
            for (int i = 0; i < 16; i++) {
                float4 kk = kr[i];
                s += q4[i].x * kk.x + q4[i].y * kk.y + q4[i].z * kk.z + q4[i].w * kk.w;
            }
            float bias;
            if (j < 3 * BLL) {
                int t = (n - 1) * BLL + j;
                bias = ltab[j];
                bool ok = (t >= 0) && (t < SS);
                if (ok) ok = (mask[b * SS + t] != 0);
                ok = ok && (maskq != 0);
                if (!ok) bias += NEGV;
            } else {
                int gI = j - 3 * BLL;
                bias = stab[gI];
                if (maskq != g_gseg[b * GLL + gI]) bias += NEGV;
            }
            sc[j2] = s + bias;
        }

        float cm = sc[0];
#pragma unroll
        for (int j2 = 1; j2 < CHUNK; j2++) cm = fmaxf(cm, sc[j2]);
        float nm = fmaxf(m, cm);
        float rs = __expf(m - nm);
        l *= rs;
#pragma unroll
        for (int i = 0; i < 16; i++) {
            acc4[i].x *= rs; acc4[i].y *= rs; acc4[i].z *= rs; acc4[i].w *= rs;
        }
#pragma unroll
        for (int j2 = 0; j2 < CHUNK; j2++) {
            float p = __expf(sc[j2] - nm);
            l += p;
            const float4* vr = (const float4*)vs[buf][j2];
#pragma unroll
            for (int i = 0; i < 16; i++) {
                float4 vv = vr[i];
                acc4[i].x += p * vv.x; acc4[i].y += p * vv.y;
                acc4[i].z += p * vv.z; acc4[i].w += p * vv.w;
            }
        }
        m = nm;
        __syncthreads();
    }

    float inv = 1.0f / l;
    float4* out = (float4*)(g_ctx + ((size_t)(b * SS + sq)) * DD + h * DKK);
#pragma unroll
    for (int i = 0; i < 16; i++) {
        float4 o = acc4[i];
        o.x *= inv; o.y *= inv; o.z *= inv; o.w *= inv;
        out[i] = o;
    }
}

// ---------------- launch ----------------
extern "C" void kernel_launch(void* const* d_in, const int* in_sizes, int n_in,
                              void* d_out, int out_size) {
    const float* hs   = (const float*)d_in[0];
    const float* Wq   = (const float*)d_in[1];
    const float* Wk   = (const float*)d_in[2];
    const float* Wv   = (const float*)d_in[3];
    const float* Wo   = (const float*)d_in[4];
    const float* relb = (const float*)d_in[5];
    const float* grel = (const float*)d_in[6];
    const float* gln  = (const float*)d_in[7];
    const int*   mask = (const int*)d_in[8];
    float* out = (float*)d_out;

    float *p_qkv, *p_skv, *p_ctx, *p_gi;
    cudaGetSymbolAddress((void**)&p_qkv, g_qkv);
    cudaGetSymbolAddress((void**)&p_skv, g_skv);
    cudaGetSymbolAddress((void**)&p_ctx, g_ctx);
    cudaGetSymbolAddress((void**)&p_gi,  g_gi);

    __nv_bfloat16 *hs_hi, *hs_lo, *ctx_hi, *ctx_lo, *gi_hi, *gi_lo;
    __nv_bfloat16 *wqkv_hi, *wqkv_lo, *wo_hi, *wo_lo;
    cudaGetSymbolAddress((void**)&hs_hi,   g_hs_hi);
    cudaGetSymbolAddress((void**)&hs_lo,   g_hs_lo);
    cudaGetSymbolAddress((void**)&ctx_hi,  g_ctx_hi);
    cudaGetSymbolAddress((void**)&ctx_lo,  g_ctx_lo);
    cudaGetSymbolAddress((void**)&gi_hi,   g_gi_hi);
    cudaGetSymbolAddress((void**)&gi_lo,   g_gi_lo);
    cudaGetSymbolAddress((void**)&wqkv_hi, g_wqkv_hi);
    cudaGetSymbolAddress((void**)&wqkv_lo, g_wqkv_lo);
    cudaGetSymbolAddress((void**)&wo_hi,   g_wo_hi);
    cudaGetSymbolAddress((void**)&wo_lo,   g_wo_lo);

    cudaFuncSetAttribute(bgemm, cudaFuncAttributeMaxDynamicSharedMemorySize, BGE_SMEM_BYTES);

    const int NHS4 = BB * SS * DD / 4;
    const int NW4  = DD * DD / 4;
    const int NGI4 = BB * GLL * DD / 4;

    // #1..#3: prerequisites for the big QKV GEMM
    k_split_qkv<<<(3 * NW4 + 255) / 256, 256>>>((const float4*)Wq, (const float4*)Wk,
                                                (const float4*)Wv, (uint2*)wqkv_hi, (uint2*)wqkv_lo);
    k_split<<<(NHS4 + 255) / 256, 256>>>((const float4*)hs, (uint2*)hs_hi, (uint2*)hs_lo, NHS4);
    k_block_ids<<<BB, 256>>>(mask);

    // #4: fused QKV GEMM (profiled slot)
    bgemm<<<dim3(3 * DD / 128, (BB * SS) / 128), 256, BGE_SMEM_BYTES>>>(
        hs_hi, hs_lo, DD, wqkv_hi, wqkv_lo, 3 * DD, p_qkv, 3 * DD, DD);

    // global path
    k_global_agg<<<dim3(GLL, BB), 256>>>(hs, gln);
    k_split<<<(NGI4 + 255) / 256, 256>>>((const float4*)p_gi, (uint2*)gi_hi, (uint2*)gi_lo, NGI4);
    bgemm<<<dim3(2 * DD / 128, (BB * GLL) / 128), 256, BGE_SMEM_BYTES>>>(
        gi_hi, gi_lo, DD, wqkv_hi + DD, wqkv_lo + DD, 3 * DD, p_skv, 2 * DD, DD);

    // bias tables + Wo split
    {
        int n1 = HH * BLL * 3 * BLL;
        k_localbias<<<(n1 + 255) / 256, 256>>>(relb);
        int n2 = HH * 257 * GLL;
        k_sidebias<<<(n2 + 255) / 256, 256>>>(grel);
    }
    k_split<<<(NW4 + 255) / 256, 256>>>((const float4*)Wo, (uint2*)wo_hi, (uint2*)wo_lo, NW4);

    // attention
    k_attn<<<dim3(HH, SS / BLL, BB), 128>>>(mask);

    // output projection
    k_split<<<(NHS4 + 255) / 256, 256>>>((const float4*)p_ctx, (uint2*)ctx_hi, (uint2*)ctx_lo, NHS4);
    bgemm<<<dim3(DD / 128, (BB * SS) / 128), 256, BGE_SMEM_BYTES>>>(
        ctx_hi, ctx_lo, DD, wo_hi, wo_lo, DD, out, DD, DD);
}

// round 8
// speedup vs baseline: 4.4882x; 2.2979x over previous
#include <cuda_runtime.h>
#include <cuda_bf16.h>
#include <cstdint>
#include <math.h>

#define BB   2
#define SS   4096
#define DD   1024
#define HH   16
#define DKK  64
#define BLL  128
#define GG   16
#define GLL  256
#define NBUCK 32
#define NEGV (-1e10f)

// ---------------- scratch (device globals: allocation-free) ----------------
__device__ float g_qkv[BB*SS*3*DD];    // [row][q|k|v]
__device__ float g_skv[BB*GLL*2*DD];   // [row][sk|sv]
__device__ float g_ctx[BB*SS*DD];
__device__ float g_gi [BB*GLL*DD];
__device__ float g_pb [HH*512];        // local rel bias table  [h][rel+255]
__device__ float g_gb [HH*512];        // global rel bias table [h][srp+255]
__device__ int   g_bid [BB*SS];
__device__ int   g_gseg[BB*GLL];
__device__ int   g_full[BB];

// bf16 hi/lo split buffers
__device__ __nv_bfloat16 g_hs_hi  [BB*SS*DD];
__device__ __nv_bfloat16 g_hs_lo  [BB*SS*DD];
__device__ __nv_bfloat16 g_ctx_hi [BB*SS*DD];
__device__ __nv_bfloat16 g_ctx_lo [BB*SS*DD];
__device__ __nv_bfloat16 g_gi_hi  [BB*GLL*DD];
__device__ __nv_bfloat16 g_gi_lo  [BB*GLL*DD];
__device__ __nv_bfloat16 g_wqkv_hi[DD*3*DD];
__device__ __nv_bfloat16 g_wqkv_lo[DD*3*DD];
__device__ __nv_bfloat16 g_wo_hi  [DD*DD];
__device__ __nv_bfloat16 g_wo_lo  [DD*DD];

// ---------------- helpers ----------------
__device__ __forceinline__ uint32_t smem_u32(const void* p) {
    uint32_t a;
    asm("{ .reg .u64 t; cvta.to.shared.u64 t, %1; cvt.u32.u64 %0, t; }" : "=r"(a) : "l"(p));
    return a;
}

#define CP16(dst, src) asm volatile("cp.async.cg.shared.global [%0], [%1], 16;" :: "r"(dst), "l"(src) : "memory")
#define CP_COMMIT()    asm volatile("cp.async.commit_group;" ::: "memory")
#define CP_WAIT1()     asm volatile("cp.async.wait_group 1;" ::: "memory")
#define CP_WAIT0()     asm volatile("cp.async.wait_group 0;" ::: "memory")

__device__ __forceinline__ void ldsm4(uint32_t* r, uint32_t a) {
    asm volatile("ldmatrix.sync.aligned.m8n8.x4.shared.b16 {%0,%1,%2,%3}, [%4];"
        : "=r"(r[0]), "=r"(r[1]), "=r"(r[2]), "=r"(r[3]) : "r"(a));
}
__device__ __forceinline__ void ldsm4t(uint32_t* r, uint32_t a) {
    asm volatile("ldmatrix.sync.aligned.m8n8.x4.trans.shared.b16 {%0,%1,%2,%3}, [%4];"
        : "=r"(r[0]), "=r"(r[1]), "=r"(r[2]), "=r"(r[3]) : "r"(a));
}
__device__ __forceinline__ void mma_bf16(float* d, const uint32_t* a, uint32_t b0, uint32_t b1) {
    asm volatile("mma.sync.aligned.m16n8k16.row.col.f32.bf16.bf16.f32 "
        "{%0,%1,%2,%3}, {%4,%5,%6,%7}, {%8,%9}, {%0,%1,%2,%3};"
        : "+f"(d[0]), "+f"(d[1]), "+f"(d[2]), "+f"(d[3])
        : "r"(a[0]), "r"(a[1]), "r"(a[2]), "r"(a[3]), "r"(b0), "r"(b1));
}

__device__ __forceinline__ void split4(float4 a, uint2& h, uint2& l) {
    __nv_bfloat162 h01 = __floats2bfloat162_rn(a.x, a.y);
    __nv_bfloat162 h23 = __floats2bfloat162_rn(a.z, a.w);
    float l0 = a.x - __bfloat162float(h01.x);
    float l1 = a.y - __bfloat162float(h01.y);
    float l2 = a.z - __bfloat162float(h23.x);
    float l3 = a.w - __bfloat162float(h23.y);
    __nv_bfloat162 q01 = __floats2bfloat162_rn(l0, l1);
    __nv_bfloat162 q23 = __floats2bfloat162_rn(l2, l3);
    h = make_uint2(*(uint32_t*)&h01, *(uint32_t*)&h23);
    l = make_uint2(*(uint32_t*)&q01, *(uint32_t*)&q23);
}

__device__ __forceinline__ void packhl(float a, float b, uint32_t& hp, uint32_t& lp) {
    __nv_bfloat162 hv = __floats2bfloat162_rn(a, b);
    __nv_bfloat162 lv = __floats2bfloat162_rn(a - __bfloat162float(hv.x),
                                              b - __bfloat162float(hv.y));
    hp = *(uint32_t*)&hv;
    lp = *(uint32_t*)&lv;
}

// ---------------- fp32 -> bf16 hi/lo split ----------------
__global__ void k_split(const float4* __restrict__ src,
                        uint2* __restrict__ hi, uint2* __restrict__ lo, int n4) {
    int i = blockIdx.x * 256 + threadIdx.x;
    if (i >= n4) return;
    uint2 h, l;
    split4(src[i], h, l);
    hi[i] = h; lo[i] = l;
}

// ---- weight split: 3 sources -> interleaved [k][3*DD] layout --------------
__global__ void k_split_qkv(const float4* __restrict__ Wq, const float4* __restrict__ Wk,
                            const float4* __restrict__ Wv,
                            uint2* __restrict__ hi, uint2* __restrict__ lo) {
    const int NW4 = DD * DD / 4;
    int idx = blockIdx.x * 256 + threadIdx.x;
    if (idx >= 3 * NW4) return;
    int i = idx / NW4;
    int r = idx % NW4;
    int k  = r >> 8;
    int n4 = r & 255;
    const float4* src = (i == 0) ? Wq : (i == 1) ? Wk : Wv;
    uint2 h, l;
    split4(src[r], h, l);
    int d = k * (3 * DD / 4) + i * (DD / 4) + n4;
    hi[d] = h; lo[d] = l;
}

// ============ bf16-split GEMM (unchanged from R7) ============
#define SH_A0   0
#define SH_A1   5120
#define SH_B0   10240
#define SH_B1   14592
#define SH_STG  18944
#define BGE_SMEM_BYTES (2 * SH_STG * 2)

__global__ __launch_bounds__(256, 2)
void bgemm(const __nv_bfloat16* __restrict__ Ahi, const __nv_bfloat16* __restrict__ Alo, int lda,
           const __nv_bfloat16* __restrict__ Bhi, const __nv_bfloat16* __restrict__ Blo, int ldb,
           float* __restrict__ C, int ldc, int K) {
    extern __shared__ __nv_bfloat16 sh[];
    uint32_t sbase = smem_u32(sh);

    int tid = threadIdx.x;
    int wid = tid >> 5, lane = tid & 31;
    int wm = wid & 3, wn = wid >> 2;
    int bx = blockIdx.x, by = blockIdx.y;

    float acc[2][8][4];
#pragma unroll
    for (int mt = 0; mt < 2; mt++)
#pragma unroll
        for (int nt = 0; nt < 8; nt++)
#pragma unroll
            for (int j = 0; j < 4; j++) acc[mt][nt][j] = 0.f;

    int ar0 = tid >> 2,          ac0 = (tid & 3) * 8;
    int ar1 = (tid + 256) >> 2,  ac1 = ((tid + 256) & 3) * 8;
    int br0 = tid >> 4,          bc0 = (tid & 15) * 8;
    int br1 = (tid + 256) >> 4,  bc1 = ((tid + 256) & 15) * 8;

    auto load_stage = [&](int c, int stage) {
        int k0 = c * 32;
        uint32_t s0 = sbase + (uint32_t)(stage * SH_STG) * 2;
        {
            size_t ga0 = (size_t)(by * 128 + ar0) * lda + k0 + ac0;
            size_t ga1 = (size_t)(by * 128 + ar1) * lda + k0 + ac1;
            uint32_t d0 = s0 + (SH_A0 + ar0 * 40 + ac0) * 2;
            uint32_t d1 = s0 + (SH_A0 + ar1 * 40 + ac1) * 2;
            CP16(d0, Ahi + ga0); CP16(d1, Ahi + ga1);
            CP16(d0 + (SH_A1 - SH_A0) * 2, Alo + ga0);
            CP16(d1 + (SH_A1 - SH_A0) * 2, Alo + ga1);
        }
        {
            size_t gb0 = (size_t)(k0 + br0) * ldb + bx * 128 + bc0;
            size_t gb1 = (size_t)(k0 + br1) * ldb + bx * 128 + bc1;
            uint32_t d0 = s0 + (SH_B0 + br0 * 136 + bc0) * 2;
            uint32_t d1 = s0 + (SH_B0 + br1 * 136 + bc1) * 2;
            CP16(d0, Bhi + gb0); CP16(d1, Bhi + gb1);
            CP16(d0 + (SH_B1 - SH_B0) * 2, Blo + gb0);
            CP16(d1 + (SH_B1 - SH_B0) * 2, Blo + gb1);
        }
        CP_COMMIT();
    };

    int nch = K >> 5;
    load_stage(0, 0);
    for (int c = 0; c < nch; c++) {
        if (c + 1 < nch) { load_stage(c + 1, (c + 1) & 1); CP_WAIT1(); }
        else             { CP_WAIT0(); }
        __syncthreads();
        uint32_t s0 = sbase + (uint32_t)((c & 1) * SH_STG) * 2;
#pragma unroll
        for (int ks = 0; ks < 2; ks++) {
            uint32_t ah[2][4], al[2][4];
#pragma unroll
            for (int mt = 0; mt < 2; mt++) {
                int row = wm * 32 + mt * 16 + (lane & 15);
                int col = ks * 16 + (lane >> 4) * 8;
                uint32_t a = s0 + (uint32_t)(SH_A0 + row * 40 + col) * 2;
                ldsm4(ah[mt], a);
                ldsm4(al[mt], a + (SH_A1 - SH_A0) * 2);
            }
#pragma unroll
            for (int nt2 = 0; nt2 < 4; nt2++) {
                uint32_t bh[4], bl[4];
                int krow = ks * 16 + (lane & 15);
                int ncol = wn * 64 + nt2 * 16 + (lane >> 4) * 8;
                uint32_t a = s0 + (uint32_t)(SH_B0 + krow * 136 + ncol) * 2;
                ldsm4t(bh, a);
                ldsm4t(bl, a + (SH_B1 - SH_B0) * 2);
#pragma unroll
                for (int p = 0; p < 2; p++) {
                    int nt = nt2 * 2 + p;
#pragma unroll
                    for (int mt = 0; mt < 2; mt++) {
                        mma_bf16(acc[mt][nt], ah[mt], bh[2 * p], bh[2 * p + 1]);
                        mma_bf16(acc[mt][nt], ah[mt], bl[2 * p], bl[2 * p + 1]);
                        mma_bf16(acc[mt][nt], al[mt], bh[2 * p], bh[2 * p + 1]);
                    }
                }
            }
        }
        __syncthreads();
    }

#pragma unroll
    for (int mt = 0; mt < 2; mt++) {
#pragma unroll
        for (int nt = 0; nt < 8; nt++) {
            int r  = by * 128 + wm * 32 + mt * 16 + (lane >> 2);
            int cc = bx * 128 + wn * 64 + nt * 8 + (lane & 3) * 2;
            *(float2*)&C[(size_t)r * ldc + cc] =
                make_float2(acc[mt][nt][0], acc[mt][nt][1]);
            *(float2*)&C[(size_t)(r + 8) * ldc + cc] =
                make_float2(acc[mt][nt][2], acc[mt][nt][3]);
        }
    }
}

// ---------------- T5 bidirectional relative bucket ----------------
__device__ __forceinline__ int rel_bucket(int rp) {
    int rb = (rp > 0) ? (NBUCK / 2) : 0;
    int a  = rp < 0 ? -rp : rp;
    if (a < 8) return rb + a;
    float rf = (float)a;
    int large = 8 + (int)(logf(rf * 0.125f) * (8.0f / 2.772588722239781f));
    if (large > 15) large = 15;
    return rb + large;
}

// ---------------- 1D bias tables ----------------
__global__ void k_pgtab(const float* __restrict__ relb, const float* __restrict__ grel) {
    int idx = blockIdx.x * 256 + threadIdx.x;
    if (idx >= HH * 512) return;
    int h = idx >> 9;
    int i = idx & 511;
    int rel = i - 255;
    int bk = rel_bucket(rel);
    g_pb[idx] = relb[bk * HH + h];
    g_gb[idx] = grel[bk * HH + h];
}

// ---------------- block ids / global segments ----------------
__global__ void k_block_ids(const int* __restrict__ mask) {
    int b = blockIdx.x;
    __shared__ int s_cnt, s_max;
    if (threadIdx.x == 0) { s_cnt = 0; s_max = -1; }
    __syncthreads();
    int lc = 0;
    for (int i = threadIdx.x; i < SS; i += blockDim.x)
        if (((i & (GG - 1)) == GG - 1) && mask[b * SS + i] != 0) lc++;
    atomicAdd(&s_cnt, lc);
    __syncthreads();
    int full = s_cnt - 1;
    int lm = -1;
    for (int i = threadIdx.x; i < SS; i += blockDim.x) {
        int id;
        if (mask[b * SS + i] != 0) { id = i / GG; if (id > full) id = full; }
        else id = -1;
        g_bid[b * SS + i] = id;
        if (id > lm) lm = id;
    }
    atomicMax(&s_max, lm);
    __syncthreads();
    for (int g = threadIdx.x; g < GLL; g += blockDim.x)
        g_gseg[b * GLL + g] = (g <= s_max) ? 1 : 0;
    if (threadIdx.x == 0) g_full[b] = full;
}

// ---------------- global aggregates + RMSNorm ----------------
__global__ void k_global_agg(const float* __restrict__ hs, const float* __restrict__ gln_w) {
    int g = blockIdx.x, b = blockIdx.y;
    int t = threadIdx.x;
    int full = g_full[b];
    float acc0 = 0.f, acc1 = 0.f, acc2 = 0.f, acc3 = 0.f;
    if (g <= full) {
        int s_begin = g * GG;
        int s_end   = (g == full) ? SS : (g + 1) * GG;
#pragma unroll 1
        for (int s = s_begin; s < s_end; s++) {
            if (g_bid[b * SS + s] == g) {
                const float* row = hs + ((size_t)(b * SS + s)) * DD;
                acc0 += row[t];
                acc1 += row[t + 256];
                acc2 += row[t + 512];
                acc3 += row[t + 768];
            }
        }
    }
    __shared__ float red[256];
    red[t] = acc0 * acc0 + acc1 * acc1 + acc2 * acc2 + acc3 * acc3;
    __syncthreads();
    for (int off = 128; off > 0; off >>= 1) {
        if (t < off) red[t] += red[t + off];
        __syncthreads();
    }
    float var = red[0] * (1.0f / (float)DD);
    float sc = rsqrtf(var + 1e-6f);
    float* out = g_gi + ((size_t)(b * GLL + g)) * DD;
    out[t]       = acc0 * sc * gln_w[t];
    out[t + 256] = acc1 * sc * gln_w[t + 256];
    out[t + 512] = acc2 * sc * gln_w[t + 512];
    out[t + 768] = acc3 * sc * gln_w[t + 768];
}

// ================= tensor-core attention =================
// one CTA per (h, n, b); 8 warps; warp w owns q rows [16w, 16w+16)
// smem (bytes):
#define ATT_QHI  0
#define ATT_QLO  18432
#define ATT_KHI  36864
#define ATT_KLO  55296
#define ATT_VHI  73728
#define ATT_VLO  92160
#define ATT_PB   110592
#define ATT_GB   112640
#define ATT_KVAL 114688
#define ATT_GSEG 115200
#define ATT_SMEM 116224

__global__ __launch_bounds__(256, 1)
void k_attn(const int* __restrict__ mask) {
    extern __shared__ char sm[];
    uint32_t sbase = smem_u32(sm);
    int h = blockIdx.x, n = blockIdx.y, b = blockIdx.z;
    int tid = threadIdx.x;
    int w = tid >> 5, lane = tid & 31;
    int g4 = lane >> 2, q4 = lane & 3;

    // ---- stage Q (bf16 hi/lo), tables, gseg ----
#pragma unroll
    for (int i = 0; i < 8; i++) {
        int f4 = i * 256 + tid;
        int row = f4 >> 4;
        int c4 = (f4 & 15) * 4;
        const float* qp = g_qkv + ((size_t)(b * SS + n * BLL + row)) * (3 * DD) + h * DKK + c4;
        float4 qv = *(const float4*)qp;
        uint2 qh, ql;
        split4(qv, qh, ql);
        uint32_t off = row * 144 + c4 * 2;
        *(uint2*)(sm + ATT_QHI + off) = qh;
        *(uint2*)(sm + ATT_QLO + off) = ql;
    }
    ((float*)(sm + ATT_PB))[tid]       = g_pb[h * 512 + tid];
    ((float*)(sm + ATT_PB))[tid + 256] = g_pb[h * 512 + tid + 256];
    ((float*)(sm + ATT_GB))[tid]       = g_gb[h * 512 + tid];
    ((float*)(sm + ATT_GB))[tid + 256] = g_gb[h * 512 + tid + 256];
    ((int*)(sm + ATT_GSEG))[tid]       = g_gseg[b * GLL + tid];

    int r0  = w * 16 + g4;
    int sq0 = n * BLL + r0;
    int mq0 = mask[b * SS + sq0], mq1 = mask[b * SS + sq0 + 8];
    int bid0 = g_bid[b * SS + sq0], bid1 = g_bid[b * SS + sq0 + 8];

    const float* pb_s   = (const float*)(sm + ATT_PB);
    const float* gb_s   = (const float*)(sm + ATT_GB);
    const int*   kval_s = (const int*)(sm + ATT_KVAL);
    const int*   gseg_s = (const int*)(sm + ATT_GSEG);

    float o[8][4];
#pragma unroll
    for (int nt = 0; nt < 8; nt++)
#pragma unroll
        for (int j = 0; j < 4; j++) o[nt][j] = 0.f;
    float m0 = -1e30f, m1 = -1e30f, l0 = 0.f, l1 = 0.f;

    for (int c = 0; c < 5; c++) {
        __syncthreads();   // previous chunk's compute done before K/V overwrite
        // ---- stage K/V chunk (128 keys) as bf16 hi/lo ----
#pragma unroll
        for (int i = 0; i < 8; i++) {
            int f4 = i * 256 + tid;
            int row = f4 >> 4;
            int c4 = (f4 & 15) * 4;
            const float *kp, *vp;
            if (c < 3) {
                int t = (n - 1 + c) * BLL + row;
                int tc = min(max(t, 0), SS - 1);
                const float* base = g_qkv + ((size_t)(b * SS + tc)) * (3 * DD) + h * DKK + c4;
                kp = base + DD; vp = base + 2 * DD;
            } else {
                int gI = (c - 3) * BLL + row;
                const float* base = g_skv + ((size_t)(b * GLL + gI)) * (2 * DD) + h * DKK + c4;
                kp = base; vp = base + DD;
            }
            float4 kv4 = *(const float4*)kp;
            float4 vv4 = *(const float4*)vp;
            uint2 kh2, kl2, vh2, vl2;
            split4(kv4, kh2, kl2);
            split4(vv4, vh2, vl2);
            uint32_t off = row * 144 + c4 * 2;
            *(uint2*)(sm + ATT_KHI + off) = kh2;
            *(uint2*)(sm + ATT_KLO + off) = kl2;
            *(uint2*)(sm + ATT_VHI + off) = vh2;
            *(uint2*)(sm + ATT_VLO + off) = vl2;
        }
        if (c < 3 && tid < BLL) {
            int t = (n - 1 + c) * BLL + tid;
            ((int*)(sm + ATT_KVAL))[tid] = (t >= 0 && t < SS) ? mask[b * SS + t] : 0;
        }
        __syncthreads();

        // ---- S = Q K^T (3-term bf16 split) ----
        float s[16][4];
#pragma unroll
        for (int nt = 0; nt < 16; nt++)
#pragma unroll
            for (int j = 0; j < 4; j++) s[nt][j] = 0.f;

#pragma unroll
        for (int kt = 0; kt < 4; kt++) {
            uint32_t qh[4], ql[4];
            uint32_t qa = sbase + ATT_QHI + (w * 16 + (lane & 15)) * 144
                        + (kt * 16 + (lane >> 4) * 8) * 2;
            ldsm4(qh, qa);
            ldsm4(ql, qa + (ATT_QLO - ATT_QHI));
#pragma unroll
            for (int nt2 = 0; nt2 < 8; nt2++) {
                uint32_t kh[4], kl[4];
                uint32_t ka = sbase + ATT_KHI + (nt2 * 16 + (lane & 15)) * 144
                            + (kt * 16 + (lane >> 4) * 8) * 2;
                ldsm4(kh, ka);
                ldsm4(kl, ka + (ATT_KLO - ATT_KHI));
                mma_bf16(s[2 * nt2],     qh, kh[0], kh[2]);
                mma_bf16(s[2 * nt2],     qh, kl[0], kl[2]);
                mma_bf16(s[2 * nt2],     ql, kh[0], kh[2]);
                mma_bf16(s[2 * nt2 + 1], qh, kh[1], kh[3]);
                mma_bf16(s[2 * nt2 + 1], qh, kl[1], kl[3]);
                mma_bf16(s[2 * nt2 + 1], ql, kh[1], kh[3]);
            }
        }

        // ---- bias + mask ----
#pragma unroll
        for (int nt = 0; nt < 16; nt++) {
            int cn = 8 * nt + 2 * q4;
            if (c < 3) {
                int kv0 = kval_s[cn], kv1 = kval_s[cn + 1];
                int rel0 = c * BLL + cn - BLL - r0;   // row r0
                int rel1 = rel0 - 8;                  // row r0+8
                s[nt][0] += pb_s[rel0 + 255] +
                    ((mq0 && kv0 && rel0 > -BLL && rel0 < BLL) ? 0.f : NEGV);
                s[nt][1] += pb_s[rel0 + 256] +
                    ((mq0 && kv1 && rel0 + 1 > -BLL && rel0 + 1 < BLL) ? 0.f : NEGV);
                s[nt][2] += pb_s[rel1 + 255] +
                    ((mq1 && kv0 && rel1 > -BLL && rel1 < BLL) ? 0.f : NEGV);
                s[nt][3] += pb_s[rel1 + 256] +
                    ((mq1 && kv1 && rel1 + 1 > -BLL && rel1 + 1 < BLL) ? 0.f : NEGV);
            } else {
                int g0 = (c - 3) * BLL + cn;
                int gs0 = gseg_s[g0], gs1 = gseg_s[g0 + 1];
                int sp0 = g0 - bid0, sp1 = g0 - bid1;
                s[nt][0] += gb_s[sp0 + 255] + ((mq0 == gs0) ? 0.f : NEGV);
                s[nt][1] += gb_s[sp0 + 256] + ((mq0 == gs1) ? 0.f : NEGV);
                s[nt][2] += gb_s[sp1 + 255] + ((mq1 == gs0) ? 0.f : NEGV);
                s[nt][3] += gb_s[sp1 + 256] + ((mq1 == gs1) ? 0.f : NEGV);
            }
        }

        // ---- online softmax (rows r0, r0+8; reduce over lane quad) ----
        float mx0 = -1e30f, mx1 = -1e30f;
#pragma unroll
        for (int nt = 0; nt < 16; nt++) {
            mx0 = fmaxf(mx0, fmaxf(s[nt][0], s[nt][1]));
            mx1 = fmaxf(mx1, fmaxf(s[nt][2], s[nt][3]));
        }
        mx0 = fmaxf(mx0, __shfl_xor_sync(0xFFFFFFFF, mx0, 1));
        mx0 = fmaxf(mx0, __shfl_xor_sync(0xFFFFFFFF, mx0, 2));
        mx1 = fmaxf(mx1, __shfl_xor_sync(0xFFFFFFFF, mx1, 1));
        mx1 = fmaxf(mx1, __shfl_xor_sync(0xFFFFFFFF, mx1, 2));
        float nm0 = fmaxf(m0, mx0), nm1 = fmaxf(m1, mx1);
        float rs0 = __expf(m0 - nm0), rs1 = __expf(m1 - nm1);
        m0 = nm0; m1 = nm1;

        float ps0 = 0.f, ps1 = 0.f;
#pragma unroll
        for (int nt = 0; nt < 16; nt++) {
            s[nt][0] = __expf(s[nt][0] - nm0); ps0 += s[nt][0];
            s[nt][1] = __expf(s[nt][1] - nm0); ps0 += s[nt][1];
            s[nt][2] = __expf(s[nt][2] - nm1); ps1 += s[nt][2];
            s[nt][3] = __expf(s[nt][3] - nm1); ps1 += s[nt][3];
        }
        ps0 += __shfl_xor_sync(0xFFFFFFFF, ps0, 1);
        ps0 += __shfl_xor_sync(0xFFFFFFFF, ps0, 2);
        ps1 += __shfl_xor_sync(0xFFFFFFFF, ps1, 1);
        ps1 += __shfl_xor_sync(0xFFFFFFFF, ps1, 2);
        l0 = l0 * rs0 + ps0;
        l1 = l1 * rs1 + ps1;

#pragma unroll
        for (int nt = 0; nt < 8; nt++) {
            o[nt][0] *= rs0; o[nt][1] *= rs0;
            o[nt][2] *= rs1; o[nt][3] *= rs1;
        }

        // ---- O += P V (P from regs as A-frags; 3-term split) ----
#pragma unroll
        for (int kt = 0; kt < 8; kt++) {
            uint32_t ahi[4], alo[4];
            packhl(s[2 * kt][0],     s[2 * kt][1],     ahi[0], alo[0]);
            packhl(s[2 * kt][2],     s[2 * kt][3],     ahi[1], alo[1]);
            packhl(s[2 * kt + 1][0], s[2 * kt + 1][1], ahi[2], alo[2]);
            packhl(s[2 * kt + 1][2], s[2 * kt + 1][3], ahi[3], alo[3]);
#pragma unroll
            for (int nt2 = 0; nt2 < 4; nt2++) {
                uint32_t vh[4], vl[4];
                uint32_t va = sbase + ATT_VHI + (kt * 16 + (lane & 15)) * 144
                            + (nt2 * 16 + (lane >> 4) * 8) * 2;
                ldsm4t(vh, va);
                ldsm4t(vl, va + (ATT_VLO - ATT_VHI));
                mma_bf16(o[2 * nt2],     ahi, vh[0], vh[1]);
                mma_bf16(o[2 * nt2],     ahi, vl[0], vl[1]);
                mma_bf16(o[2 * nt2],     alo, vh[0], vh[1]);
                mma_bf16(o[2 * nt2 + 1], ahi, vh[2], vh[3]);
                mma_bf16(o[2 * nt2 + 1], ahi, vl[2], vl[3]);
                mma_bf16(o[2 * nt2 + 1], alo, vh[2], vh[3]);
            }
        }
    }

    // ---- epilogue ----
    float inv0 = 1.0f / l0, inv1 = 1.0f / l1;
    float* ctx0 = g_ctx + ((size_t)(b * SS + sq0)) * DD + h * DKK;
    float* ctx1 = g_ctx + ((size_t)(b * SS + sq0 + 8)) * DD + h * DKK;
#pragma unroll
    for (int nt = 0; nt < 8; nt++) {
        int cc = 8 * nt + 2 * q4;
        *(float2*)(ctx0 + cc) = make_float2(o[nt][0] * inv0, o[nt][1] * inv0);
        *(float2*)(ctx1 + cc) = make_float2(o[nt][2] * inv1, o[nt][3] * inv1);
    }
}

// ---------------- launch ----------------
extern "C" void kernel_launch(void* const* d_in, const int* in_sizes, int n_in,
                              void* d_out, int out_size) {
    const float* hs   = (const float*)d_in[0];
    const float* Wq   = (const float*)d_in[1];
    const float* Wk   = (const float*)d_in[2];
    const float* Wv   = (const float*)d_in[3];
    const float* Wo   = (const float*)d_in[4];
    const float* relb = (const float*)d_in[5];
    const float* grel = (const float*)d_in[6];
    const float* gln  = (const float*)d_in[7];
    const int*   mask = (const int*)d_in[8];
    float* out = (float*)d_out;

    float *p_qkv, *p_skv, *p_ctx, *p_gi;
    cudaGetSymbolAddress((void**)&p_qkv, g_qkv);
    cudaGetSymbolAddress((void**)&p_skv, g_skv);
    cudaGetSymbolAddress((void**)&p_ctx, g_ctx);
    cudaGetSymbolAddress((void**)&p_gi,  g_gi);

    __nv_bfloat16 *hs_hi, *hs_lo, *ctx_hi, *ctx_lo, *gi_hi, *gi_lo;
    __nv_bfloat16 *wqkv_hi, *wqkv_lo, *wo_hi, *wo_lo;
    cudaGetSymbolAddress((void**)&hs_hi,   g_hs_hi);
    cudaGetSymbolAddress((void**)&hs_lo,   g_hs_lo);
    cudaGetSymbolAddress((void**)&ctx_hi,  g_ctx_hi);
    cudaGetSymbolAddress((void**)&ctx_lo,  g_ctx_lo);
    cudaGetSymbolAddress((void**)&gi_hi,   g_gi_hi);
    cudaGetSymbolAddress((void**)&gi_lo,   g_gi_lo);
    cudaGetSymbolAddress((void**)&wqkv_hi, g_wqkv_hi);
    cudaGetSymbolAddress((void**)&wqkv_lo, g_wqkv_lo);
    cudaGetSymbolAddress((void**)&wo_hi,   g_wo_hi);
    cudaGetSymbolAddress((void**)&wo_lo,   g_wo_lo);

    cudaFuncSetAttribute(bgemm, cudaFuncAttributeMaxDynamicSharedMemorySize, BGE_SMEM_BYTES);
    cudaFuncSetAttribute(k_attn, cudaFuncAttributeMaxDynamicSharedMemorySize, ATT_SMEM);

    const int NHS4 = BB * SS * DD / 4;
    const int NW4  = DD * DD / 4;
    const int NGI4 = BB * GLL * DD / 4;

    // #1..#3: prerequisites for the big QKV GEMM
    k_split_qkv<<<(3 * NW4 + 255) / 256, 256>>>((const float4*)Wq, (const float4*)Wk,
                                                (const float4*)Wv, (uint2*)wqkv_hi, (uint2*)wqkv_lo);
    k_split<<<(NHS4 + 255) / 256, 256>>>((const float4*)hs, (uint2*)hs_hi, (uint2*)hs_lo, NHS4);
    k_block_ids<<<BB, 256>>>(mask);

    // #4: fused QKV GEMM (profiled slot)
    bgemm<<<dim3(3 * DD / 128, (BB * SS) / 128), 256, BGE_SMEM_BYTES>>>(
        hs_hi, hs_lo, DD, wqkv_hi, wqkv_lo, 3 * DD, p_qkv, 3 * DD, DD);

    // global path
    k_global_agg<<<dim3(GLL, BB), 256>>>(hs, gln);
    k_split<<<(NGI4 + 255) / 256, 256>>>((const float4*)p_gi, (uint2*)gi_hi, (uint2*)gi_lo, NGI4);
    bgemm<<<dim3(2 * DD / 128, (BB * GLL) / 128), 256, BGE_SMEM_BYTES>>>(
        gi_hi, gi_lo, DD, wqkv_hi + DD, wqkv_lo + DD, 3 * DD, p_skv, 2 * DD, DD);

    // bias tables + Wo split
    k_pgtab<<<(HH * 512 + 255) / 256, 256>>>(relb, grel);
    k_split<<<(NW4 + 255) / 256, 256>>>((const float4*)Wo, (uint2*)wo_hi, (uint2*)wo_lo, NW4);

    // attention (tensor-core)
    k_attn<<<dim3(HH, SS / BLL, BB), 256, ATT_SMEM>>>(mask);

    // output projection
    k_split<<<(NHS4 + 255) / 256, 256>>>((const float4*)p_ctx, (uint2*)ctx_hi, (uint2*)ctx_lo, NHS4);
    bgemm<<<dim3(DD / 128, (BB * SS) / 128), 256, BGE_SMEM_BYTES>>>(
        ctx_hi, ctx_lo, DD, wo_hi, wo_lo, DD, out, DD, DD);
}